// round 12
// baseline (speedup 1.0000x reference)
#include <cuda_runtime.h>
#include <cuda_fp16.h>
#include <cstdint>
#include <cstddef>

#define S_LEN 4096
#define BATCH 2
#define EMB   1024
#define HEADS 8
#define HD    128
#define WINW  256
#define SPAD  (S_LEN + 2*WINW)   // 4608

// fp16 Q (hi only) and split-fp16 K/V in attention layout
__device__ __align__(16) __half g_Qh[BATCH*HEADS*S_LEN*HD];
__device__ __align__(16) __half g_Kh[BATCH*HEADS*SPAD*HD];
__device__ __align__(16) __half g_Kl[BATCH*HEADS*SPAD*HD];
__device__ __align__(16) __half g_Vh[BATCH*HEADS*SPAD*HD];
__device__ __align__(16) __half g_Vl[BATCH*HEADS*SPAD*HD];

// GEMM inputs: X hi-only, W split hi/lo
__device__ __align__(16) __half g_Xh[8192*1024];
__device__ __align__(16) __half g_Wh[3*1024*1024];
__device__ __align__(16) __half g_Wl[3*1024*1024];

// ---------------------------------------------------------------------------
// helpers
// ---------------------------------------------------------------------------
__device__ __forceinline__ uint32_t smem_to_u32(const void* p) {
    uint32_t a;
    asm("{ .reg .u64 t; cvta.to.shared.u64 t, %1; cvt.u32.u64 %0, t; }"
        : "=r"(a) : "l"(p));
    return a;
}
__device__ __forceinline__ void cp_async16(uint32_t dst, const void* src) {
    asm volatile("cp.async.cg.shared.global [%0], [%1], 16;"
                 :: "r"(dst), "l"(src) : "memory");
}
#define CP_COMMIT() asm volatile("cp.async.commit_group;" ::: "memory")
#define CP_WAIT0()  asm volatile("cp.async.wait_group 0;" ::: "memory")
#define CP_WAIT1()  asm volatile("cp.async.wait_group 1;" ::: "memory")

__device__ __forceinline__ void ldmatrix_x4(uint32_t* r, uint32_t addr) {
    asm volatile("ldmatrix.sync.aligned.m8n8.x4.shared.b16 {%0,%1,%2,%3}, [%4];"
                 : "=r"(r[0]), "=r"(r[1]), "=r"(r[2]), "=r"(r[3]) : "r"(addr));
}
__device__ __forceinline__ void ldmatrix_x4_trans(uint32_t* r, uint32_t addr) {
    asm volatile("ldmatrix.sync.aligned.m8n8.x4.trans.shared.b16 {%0,%1,%2,%3}, [%4];"
                 : "=r"(r[0]), "=r"(r[1]), "=r"(r[2]), "=r"(r[3]) : "r"(addr));
}
__device__ __forceinline__ void mma16816(float* c, const uint32_t* a,
                                         const uint32_t* b) {
    asm volatile(
        "mma.sync.aligned.m16n8k16.row.col.f32.f16.f16.f32 "
        "{%0,%1,%2,%3}, {%4,%5,%6,%7}, {%8,%9}, {%0,%1,%2,%3};"
        : "+f"(c[0]), "+f"(c[1]), "+f"(c[2]), "+f"(c[3])
        : "r"(a[0]), "r"(a[1]), "r"(a[2]), "r"(a[3]), "r"(b[0]), "r"(b[1]));
}
__device__ __forceinline__ uint32_t pack_f16x2(float lo, float hi) {
    uint32_t r;
    asm("cvt.rn.f16x2.f32 %0, %1, %2;" : "=r"(r) : "f"(hi), "f"(lo));
    return r;
}

// ---------------------------------------------------------------------------
// Converts: X -> fp16 hi (with view-scramble gather); W -> fp16 hi/lo split
// ---------------------------------------------------------------------------
__global__ void convert_x_kernel(const float* __restrict__ val)
{
    int i = blockIdx.x * blockDim.x + threadIdx.x;
    if (i >= 8192*1024) return;
    int r = i >> 10, k = i & 1023;
    int b = r >> 12, s = r & 4095;
    g_Xh[i] = __float2half_rn(val[s*2048 + b*1024 + k]);
}

__global__ void convert_w_kernel(const float* __restrict__ Wq,
                                 const float* __restrict__ Wk,
                                 const float* __restrict__ Wv)
{
    int i = blockIdx.x * blockDim.x + threadIdx.x;
    if (i >= 3*1024*1024) return;
    int mat = i >> 20;
    const float* W = (mat == 0) ? Wq : (mat == 1 ? Wk : Wv);
    float f = W[i & 0xFFFFF];
    __half h = __float2half_rn(f);
    g_Wh[i] = h;
    g_Wl[i] = __float2half_rn(f - __half2float(h));
}

// ---------------------------------------------------------------------------
// Zero the pad rows of K/V
// ---------------------------------------------------------------------------
__global__ void zero_pads_kernel()
{
    int i = blockIdx.x * blockDim.x + threadIdx.x;
    const int total = BATCH*HEADS * (2*WINW) * HD;
    if (i >= total) return;
    int d  = i & (HD-1);
    int t  = i >> 7;
    int jr = t & (2*WINW - 1);
    int bh = t >> 9;
    int jpad = (jr < WINW) ? jr : (S_LEN + jr);
    size_t off = ((size_t)bh*SPAD + jpad)*HD + d;
    __half z = __float2half_rn(0.0f);
    g_Kh[off] = z; g_Kl[off] = z;
    g_Vh[off] = z; g_Vl[off] = z;
}

// ---------------------------------------------------------------------------
// Warp-MMA GEMM: C = X @ W^T + bias; fp16 2-product scheme (Xh*Wh + Xh*Wl).
// CTA 128x128, K-tile 32, cp.async double buffer. Stage = [Ah, Bh, Bl].
// ---------------------------------------------------------------------------
#define BK 32
#define NKT 32                    // 1024 / 32
#define LDSTR 40                  // smem row stride in fp16 (80 B)
#define VAR_BYTES (128*LDSTR*2)   // 10240
#define STAGE_BYTES (3*VAR_BYTES) // 30720: [Ah, Bh, Bl]
#define GEMM_SMEM (2*STAGE_BYTES) // 61440

__global__ __launch_bounds__(256) void qkv_mma_kernel(
    const float* __restrict__ bq, const float* __restrict__ bk,
    const float* __restrict__ bv)
{
    extern __shared__ char smem[];
    const uint32_t smem_base = smem_to_u32(smem);
    const int tid  = threadIdx.x;
    const int wid  = tid >> 5;
    const int lane = tid & 31;

    const int col0 = blockIdx.x * 128;
    const int row0 = blockIdx.y * 128;
    const int mat  = blockIdx.z;
    const float* bia = (mat == 0) ? bq : (mat == 1 ? bk : bv);

    const __half* Wh = g_Wh + (size_t)mat * 1048576;
    const __half* Wl = g_Wl + (size_t)mat * 1048576;

    const int ch0_row = tid >> 2,         ch0_quad = tid & 3;
    const int ch1_row = (tid + 256) >> 2, ch1_quad = (tid + 256) & 3;

    const __half* srcs[3] = { g_Xh, Wh, Wl };
    const int vrow0[3] = { row0, col0, col0 };

    const int warp_m0 = (wid & 3) * 32;
    const int warp_n0 = (wid >> 2) * 64;

    const int offA_row = (lane & 7) + (lane & 8);
    const int offA_k   = (lane & 16) >> 1;
    const int offB_row = (lane & 7) + ((lane & 16) >> 1);
    const int offB_k   = lane & 8;

    float acc[2][8][4];
    #pragma unroll
    for (int mt = 0; mt < 2; mt++)
        #pragma unroll
        for (int nf = 0; nf < 8; nf++)
            acc[mt][nf][0] = acc[mt][nf][1] = acc[mt][nf][2] = acc[mt][nf][3] = 0.f;

    {
        const uint32_t sb = smem_base;
        #pragma unroll
        for (int v = 0; v < 3; v++) {
            cp_async16(sb + v*VAR_BYTES + (ch0_row*LDSTR + ch0_quad*8)*2,
                       srcs[v] + (size_t)(vrow0[v] + ch0_row)*1024 + ch0_quad*8);
            cp_async16(sb + v*VAR_BYTES + (ch1_row*LDSTR + ch1_quad*8)*2,
                       srcs[v] + (size_t)(vrow0[v] + ch1_row)*1024 + ch1_quad*8);
        }
        CP_COMMIT();
    }

    for (int kt = 0; kt < NKT; kt++) {
        if (kt + 1 < NKT) {
            const uint32_t sb = smem_base + ((kt+1) & 1) * STAGE_BYTES;
            const int k0 = (kt+1) * BK;
            #pragma unroll
            for (int v = 0; v < 3; v++) {
                cp_async16(sb + v*VAR_BYTES + (ch0_row*LDSTR + ch0_quad*8)*2,
                           srcs[v] + (size_t)(vrow0[v] + ch0_row)*1024 + k0 + ch0_quad*8);
                cp_async16(sb + v*VAR_BYTES + (ch1_row*LDSTR + ch1_quad*8)*2,
                           srcs[v] + (size_t)(vrow0[v] + ch1_row)*1024 + k0 + ch1_quad*8);
            }
            CP_COMMIT();
            CP_WAIT1();
        } else {
            CP_WAIT0();
        }
        __syncthreads();

        const uint32_t sb = smem_base + (kt & 1) * STAGE_BYTES;
        const uint32_t aH = sb;
        const uint32_t bH = sb + VAR_BYTES, bL = sb + 2*VAR_BYTES;

        #pragma unroll
        for (int ks = 0; ks < 2; ks++) {
            const int kk = ks * 16;
            uint32_t ahf[2][4];
            #pragma unroll
            for (int mt = 0; mt < 2; mt++) {
                const uint32_t ro = (uint32_t)((warp_m0 + mt*16 + offA_row)*LDSTR
                                               + kk + offA_k) * 2;
                ldmatrix_x4(ahf[mt], aH + ro);
            }
            #pragma unroll
            for (int np = 0; np < 4; np++) {
                uint32_t bh4[4], bl4[4];
                const uint32_t ro = (uint32_t)((warp_n0 + np*16 + offB_row)*LDSTR
                                               + kk + offB_k) * 2;
                ldmatrix_x4(bh4, bH + ro);
                ldmatrix_x4(bl4, bL + ro);
                #pragma unroll
                for (int mt = 0; mt < 2; mt++) {
                    mma16816(acc[mt][2*np],   ahf[mt], &bh4[0]);
                    mma16816(acc[mt][2*np],   ahf[mt], &bl4[0]);
                    mma16816(acc[mt][2*np+1], ahf[mt], &bh4[2]);
                    mma16816(acc[mt][2*np+1], ahf[mt], &bl4[2]);
                }
            }
        }
        __syncthreads();
    }

    // ---- epilogue: bias (+Q scale), fp16 write, view-scramble scatter ----
    const float scale = 0.08838834764831845f;   // 1/sqrt(128)
    #pragma unroll
    for (int mt = 0; mt < 2; mt++) {
        #pragma unroll
        for (int nf = 0; nf < 8; nf++) {
            const int col = col0 + warp_n0 + nf*8 + (lane & 3)*2;
            const int h   = col >> 7;
            const int dd  = col & 127;
            const float b0 = bia[col], b1 = bia[col+1];
            #pragma unroll
            for (int half_i = 0; half_i < 2; half_i++) {
                const int r  = row0 + warp_m0 + mt*16 + (lane >> 2) + half_i*8;
                const int bp = r & 1;
                const int sp = r >> 1;
                float v0 = acc[mt][nf][half_i*2+0] + b0;
                float v1 = acc[mt][nf][half_i*2+1] + b1;
                if (mat == 0) {
                    v0 *= scale; v1 *= scale;
                    const size_t idx = ((size_t)(bp*HEADS + h)*S_LEN + sp)*HD + dd;
                    __half2 hv;
                    hv.x = __float2half_rn(v0); hv.y = __float2half_rn(v1);
                    *(__half2*)(g_Qh + idx) = hv;
                } else {
                    const size_t idx = ((size_t)(bp*HEADS + h)*SPAD + (sp + WINW))*HD + dd;
                    __half* ah = (mat == 1) ? g_Kh : g_Vh;
                    __half* al = (mat == 1) ? g_Kl : g_Vl;
                    __half h0 = __float2half_rn(v0);
                    __half h1 = __float2half_rn(v1);
                    __half2 hv; hv.x = h0; hv.y = h1;
                    __half2 lv;
                    lv.x = __float2half_rn(v0 - __half2float(h0));
                    lv.y = __float2half_rn(v1 - __half2float(h1));
                    *(__half2*)(ah + idx) = hv;
                    *(__half2*)(al + idx) = lv;
                }
            }
        }
    }
}

// ---------------------------------------------------------------------------
// Banded flash attention via mma.sync, fp16 2-product:
//  S = Qh*(Kh+Kl), O += Ph*(Vh+Vl). Q frags register-cached; KV double-buffered.
// CTA = 128 queries of one (b',h); 8 warps x 16 queries; 10 chunks of 64 keys.
// ---------------------------------------------------------------------------
#define SSTR 136                       // smem row stride in fp16 (272 B)
#define QV_BYTES (128*SSTR*2)          // 34816 (Q hi only)
#define KV_VAR   (64*SSTR*2)           // 17408 per KV var
#define KV_STAGE (4*KV_VAR)            // 69632: [Kh, Kl, Vh, Vl]
#define ATT_SMEM (QV_BYTES + 2*KV_STAGE)   // 174080

__global__ __launch_bounds__(256, 1) void attn_mma_kernel(float* __restrict__ out)
{
    extern __shared__ char smem[];
    const uint32_t sb = smem_to_u32(smem);
    const uint32_t sQh = sb;
    const uint32_t sKV = sb + QV_BYTES;       // two stages of [Kh,Kl,Vh,Vl]

    const int s0  = blockIdx.x * 128;
    const int h   = blockIdx.y;
    const int bp  = blockIdx.z;
    const int bh  = bp*HEADS + h;
    const int tid = threadIdx.x;
    const int wid = tid >> 5;
    const int lane = tid & 31;

    const __half* Qhg = g_Qh + ((size_t)bh*S_LEN + s0)*HD;
    const size_t kvbase = ((size_t)bh*SPAD + s0)*HD;
    const __half* gKV[4] = {
        g_Kh + kvbase, g_Kl + kvbase, g_Vh + kvbase, g_Vl + kvbase };

    // stage Q via cp.async (group 0): 128 rows x 128 fp16 = 2048 chunks
    #pragma unroll
    for (int t = 0; t < 8; t++) {
        const int i = tid + t*256;
        const int row = i >> 4, ch = i & 15;
        cp_async16(sQh + row*272 + ch*16, Qhg + (size_t)row*HD + ch*8);
    }
    CP_COMMIT();

    // prefetch KV chunk 0 into stage 0 (group 1)
    #pragma unroll
    for (int t = 0; t < 16; t++) {
        const int i = tid + t*256;
        const int v = i >> 10, idx = i & 1023;
        const int row = idx >> 4, ch = idx & 15;
        cp_async16(sKV + v*KV_VAR + row*272 + ch*16,
                   gKV[v] + (size_t)row*HD + ch*8);
    }
    CP_COMMIT();

    const int warp_q0 = wid * 16;
    const int offA_row = (lane & 7) + (lane & 8);
    const int offA_k   = (lane & 16) >> 1;
    const int offB_row = (lane & 7) + ((lane & 16) >> 1);
    const int offB_k   = lane & 8;
    const int vt_r = lane & 7;
    const int vt_j = ((lane >> 3) & 1) * 8;
    const int vt_d = ((lane >> 4) & 1) * 8;

    const int qlo = warp_q0 + (lane >> 2);
    const int qhi = qlo + 8;

    CP_WAIT1();            // Q ready (chunk 0 may still be in flight)
    __syncthreads();

    // cache Q fragments in registers for all 8 k-steps
    uint32_t qh[8][4];
    #pragma unroll
    for (int ks = 0; ks < 8; ks++) {
        const uint32_t qo = (uint32_t)((warp_q0 + offA_row)*SSTR
                                       + ks*16 + offA_k) * 2;
        ldmatrix_x4(qh[ks], sQh + qo);
    }

    float of[16][4];
    #pragma unroll
    for (int f = 0; f < 16; f++)
        of[f][0] = of[f][1] = of[f][2] = of[f][3] = 0.f;
    float m_lo = -1e30f, m_hi = -1e30f, l_lo = 0.f, l_hi = 0.f;

    for (int c = 0; c < 10; c++) {
        if (c < 9) {
            const uint32_t dstS = sKV + ((c+1) & 1) * KV_STAGE;
            const size_t srcOff = (size_t)(c+1)*64*HD;
            #pragma unroll
            for (int t = 0; t < 16; t++) {
                const int i = tid + t*256;
                const int v = i >> 10, idx = i & 1023;
                const int row = idx >> 4, ch = idx & 15;
                cp_async16(dstS + v*KV_VAR + row*272 + ch*16,
                           gKV[v] + srcOff + (size_t)row*HD + ch*8);
            }
            CP_COMMIT();
            CP_WAIT1();
        } else {
            CP_WAIT0();
        }
        __syncthreads();

        const uint32_t stg = sKV + (c & 1) * KV_STAGE;
        const uint32_t cKh = stg, cKl = stg + KV_VAR;
        const uint32_t cVh = stg + 2*KV_VAR, cVl = stg + 3*KV_VAR;

        // ---- S = Qh (Kh + Kl)^T (64 keys), fp32 accum ----
        float sf[8][4];
        #pragma unroll
        for (int f = 0; f < 8; f++)
            sf[f][0] = sf[f][1] = sf[f][2] = sf[f][3] = 0.f;

        #pragma unroll
        for (int ks = 0; ks < 8; ks++) {
            #pragma unroll
            for (int ng = 0; ng < 4; ng++) {
                uint32_t kh4[4], kl4[4];
                const uint32_t ko = (uint32_t)((ng*16 + offB_row)*SSTR
                                               + ks*16 + offB_k) * 2;
                ldmatrix_x4(kh4, cKh + ko);
                ldmatrix_x4(kl4, cKl + ko);
                mma16816(sf[2*ng],   qh[ks], &kh4[0]);
                mma16816(sf[2*ng],   qh[ks], &kl4[0]);
                mma16816(sf[2*ng+1], qh[ks], &kh4[2]);
                mma16816(sf[2*ng+1], qh[ks], &kl4[2]);
            }
        }

        // ---- masked online softmax ----
        const int kb = c*64 + (lane & 3)*2;
        float mxlo = -1e30f, mxhi = -1e30f;
        #pragma unroll
        for (int f = 0; f < 8; f++) {
            #pragma unroll
            for (int j = 0; j < 2; j++) {
                const int kc = kb + f*8 + j;
                const bool vlo = (kc >= qlo) && (kc <= qlo + 512);
                const bool vhi = (kc >= qhi) && (kc <= qhi + 512);
                const float slo = vlo ? sf[f][j]   : -1e30f;
                const float shi = vhi ? sf[f][2+j] : -1e30f;
                sf[f][j]   = slo;  mxlo = fmaxf(mxlo, slo);
                sf[f][2+j] = shi;  mxhi = fmaxf(mxhi, shi);
            }
        }
        mxlo = fmaxf(mxlo, __shfl_xor_sync(0xffffffffu, mxlo, 1));
        mxlo = fmaxf(mxlo, __shfl_xor_sync(0xffffffffu, mxlo, 2));
        mxhi = fmaxf(mxhi, __shfl_xor_sync(0xffffffffu, mxhi, 1));
        mxhi = fmaxf(mxhi, __shfl_xor_sync(0xffffffffu, mxhi, 2));

        const float mnlo = fmaxf(m_lo, mxlo);
        const float mnhi = fmaxf(m_hi, mxhi);
        const float alo = __expf(m_lo - mnlo);
        const float ahi = __expf(m_hi - mnhi);
        m_lo = mnlo; m_hi = mnhi;

        float sumlo = 0.f, sumhi = 0.f;
        #pragma unroll
        for (int f = 0; f < 8; f++) {
            #pragma unroll
            for (int j = 0; j < 2; j++) {
                const int kc = kb + f*8 + j;
                const bool vlo = (kc >= qlo) && (kc <= qlo + 512);
                const bool vhi = (kc >= qhi) && (kc <= qhi + 512);
                const float plo = vlo ? __expf(sf[f][j]   - mnlo) : 0.f;
                const float phi = vhi ? __expf(sf[f][2+j] - mnhi) : 0.f;
                sf[f][j] = plo;   sumlo += plo;
                sf[f][2+j] = phi; sumhi += phi;
            }
        }
        sumlo += __shfl_xor_sync(0xffffffffu, sumlo, 1);
        sumlo += __shfl_xor_sync(0xffffffffu, sumlo, 2);
        sumhi += __shfl_xor_sync(0xffffffffu, sumhi, 1);
        sumhi += __shfl_xor_sync(0xffffffffu, sumhi, 2);
        l_lo = l_lo*alo + sumlo;
        l_hi = l_hi*ahi + sumhi;

        #pragma unroll
        for (int f = 0; f < 16; f++) {
            of[f][0] *= alo; of[f][1] *= alo;
            of[f][2] *= ahi; of[f][3] *= ahi;
        }

        // ---- O += Ph (Vh + Vl) ----
        #pragma unroll
        for (int t = 0; t < 4; t++) {
            uint32_t ah[4];
            #pragma unroll
            for (int g = 0; g < 4; g++) {
                const int fr = 2*t + (g >> 1);
                const int b0 = (g & 1) * 2;
                ah[g] = pack_f16x2(sf[fr][b0], sf[fr][b0+1]);
            }
            #pragma unroll
            for (int dg = 0; dg < 8; dg++) {
                uint32_t vh4[4], vl4[4];
                const uint32_t vo = (uint32_t)((t*16 + vt_j + vt_r)*SSTR
                                               + dg*16 + vt_d) * 2;
                ldmatrix_x4_trans(vh4, cVh + vo);
                ldmatrix_x4_trans(vl4, cVl + vo);
                mma16816(of[2*dg],   ah, &vh4[0]);
                mma16816(of[2*dg],   ah, &vl4[0]);
                mma16816(of[2*dg+1], ah, &vh4[2]);
                mma16816(of[2*dg+1], ah, &vl4[2]);
            }
        }
        __syncthreads();
    }

    // ---- write out: out[s'][b'][h*128+d] ----
    const float invlo = 1.f / l_lo;
    const float invhi = 1.f / l_hi;
    const int sqlo = s0 + qlo;
    const int sqhi = s0 + qhi;
    const size_t obase = (size_t)bp*1024 + h*128 + (lane & 3)*2;
    #pragma unroll
    for (int f = 0; f < 16; f++) {
        const int d = f*8;
        float2 o1; o1.x = of[f][0]*invlo; o1.y = of[f][1]*invlo;
        *(float2*)&out[(size_t)sqlo*2048 + obase + d] = o1;
        float2 o2; o2.x = of[f][2]*invhi; o2.y = of[f][3]*invhi;
        *(float2*)&out[(size_t)sqhi*2048 + obase + d] = o2;
    }
}

// ---------------------------------------------------------------------------
extern "C" void kernel_launch(void* const* d_in, const int* in_sizes, int n_in,
                              void* d_out, int out_size)
{
    (void)in_sizes; (void)n_in; (void)out_size;
    const float* val = (const float*)d_in[0];
    const float* Wq  = (const float*)d_in[1];
    const float* bq  = (const float*)d_in[2];
    const float* Wk  = (const float*)d_in[3];
    const float* bk  = (const float*)d_in[4];
    const float* Wv  = (const float*)d_in[5];
    const float* bv  = (const float*)d_in[6];
    float* out = (float*)d_out;

    cudaFuncSetAttribute(qkv_mma_kernel, cudaFuncAttributeMaxDynamicSharedMemorySize,
                         GEMM_SMEM);
    cudaFuncSetAttribute(attn_mma_kernel, cudaFuncAttributeMaxDynamicSharedMemorySize,
                         ATT_SMEM);

    convert_x_kernel<<<(8192*1024)/256, 256>>>(val);
    convert_w_kernel<<<(3*1024*1024)/256, 256>>>(Wq, Wk, Wv);
    {
        const int total = BATCH*HEADS * (2*WINW) * HD;
        zero_pads_kernel<<<(total + 255)/256, 256>>>();
    }
    {
        dim3 grid(1024/128, 8192/128, 3);
        qkv_mma_kernel<<<grid, 256, GEMM_SMEM>>>(bq, bk, bv);
    }
    {
        dim3 grid(S_LEN/128, HEADS, BATCH);
        attn_mma_kernel<<<grid, 256, ATT_SMEM>>>(out);
    }
}

// round 14
// speedup vs baseline: 1.1659x; 1.1659x over previous
#include <cuda_runtime.h>
#include <cuda_bf16.h>
#include <cstdint>
#include <cstddef>

#define S_LEN 4096
#define BATCH 2
#define EMB   1024
#define HEADS 8
#define HD    128
#define WINW  256
#define SPAD  (S_LEN + 2*WINW)   // 4608

// Split-bf16 Q/K/V in attention layout (written by GEMM epilogue)
__device__ __align__(16) __nv_bfloat16 g_Qh[BATCH*HEADS*S_LEN*HD];
__device__ __align__(16) __nv_bfloat16 g_Ql[BATCH*HEADS*S_LEN*HD];
__device__ __align__(16) __nv_bfloat16 g_Kh[BATCH*HEADS*SPAD*HD];
__device__ __align__(16) __nv_bfloat16 g_Kl[BATCH*HEADS*SPAD*HD];
__device__ __align__(16) __nv_bfloat16 g_Vh[BATCH*HEADS*SPAD*HD];
__device__ __align__(16) __nv_bfloat16 g_Vl[BATCH*HEADS*SPAD*HD];

// Split-bf16 GEMM inputs
__device__ __align__(16) __nv_bfloat16 g_Xh[8192*1024];
__device__ __align__(16) __nv_bfloat16 g_Xl[8192*1024];
__device__ __align__(16) __nv_bfloat16 g_Wh[3*1024*1024];
__device__ __align__(16) __nv_bfloat16 g_Wl[3*1024*1024];

// ---------------------------------------------------------------------------
// helpers
// ---------------------------------------------------------------------------
__device__ __forceinline__ uint32_t smem_to_u32(const void* p) {
    uint32_t a;
    asm("{ .reg .u64 t; cvta.to.shared.u64 t, %1; cvt.u32.u64 %0, t; }"
        : "=r"(a) : "l"(p));
    return a;
}
__device__ __forceinline__ void cp_async16(uint32_t dst, const void* src) {
    asm volatile("cp.async.cg.shared.global [%0], [%1], 16;"
                 :: "r"(dst), "l"(src) : "memory");
}
#define CP_COMMIT() asm volatile("cp.async.commit_group;" ::: "memory")
#define CP_WAIT0()  asm volatile("cp.async.wait_group 0;" ::: "memory")
#define CP_WAIT1()  asm volatile("cp.async.wait_group 1;" ::: "memory")

__device__ __forceinline__ void ldmatrix_x4(uint32_t* r, uint32_t addr) {
    asm volatile("ldmatrix.sync.aligned.m8n8.x4.shared.b16 {%0,%1,%2,%3}, [%4];"
                 : "=r"(r[0]), "=r"(r[1]), "=r"(r[2]), "=r"(r[3]) : "r"(addr));
}
__device__ __forceinline__ void ldmatrix_x4_trans(uint32_t* r, uint32_t addr) {
    asm volatile("ldmatrix.sync.aligned.m8n8.x4.trans.shared.b16 {%0,%1,%2,%3}, [%4];"
                 : "=r"(r[0]), "=r"(r[1]), "=r"(r[2]), "=r"(r[3]) : "r"(addr));
}
__device__ __forceinline__ void mma16816(float* c, const uint32_t* a,
                                         const uint32_t* b) {
    asm volatile(
        "mma.sync.aligned.m16n8k16.row.col.f32.bf16.bf16.f32 "
        "{%0,%1,%2,%3}, {%4,%5,%6,%7}, {%8,%9}, {%0,%1,%2,%3};"
        : "+f"(c[0]), "+f"(c[1]), "+f"(c[2]), "+f"(c[3])
        : "r"(a[0]), "r"(a[1]), "r"(a[2]), "r"(a[3]), "r"(b[0]), "r"(b[1]));
}
__device__ __forceinline__ uint32_t pack_bf16x2(float lo, float hi) {
    uint32_t r;
    asm("cvt.rn.bf16x2.f32 %0, %1, %2;" : "=r"(r) : "f"(hi), "f"(lo));
    return r;
}

// ---------------------------------------------------------------------------
// Split fp32 -> (bf16 hi, bf16 lo). X rows are the view-scramble gather.
// ---------------------------------------------------------------------------
__global__ void convert_x_kernel(const float* __restrict__ val)
{
    int i = blockIdx.x * blockDim.x + threadIdx.x;
    if (i >= 8192*1024) return;
    int r = i >> 10, k = i & 1023;
    int b = r >> 12, s = r & 4095;
    float f = val[s*2048 + b*1024 + k];
    __nv_bfloat16 h = __float2bfloat16(f);
    g_Xh[i] = h;
    g_Xl[i] = __float2bfloat16(f - __bfloat162float(h));
}

__global__ void convert_w_kernel(const float* __restrict__ Wq,
                                 const float* __restrict__ Wk,
                                 const float* __restrict__ Wv)
{
    int i = blockIdx.x * blockDim.x + threadIdx.x;
    if (i >= 3*1024*1024) return;
    int mat = i >> 20;
    const float* W = (mat == 0) ? Wq : (mat == 1 ? Wk : Wv);
    float f = W[i & 0xFFFFF];
    __nv_bfloat16 h = __float2bfloat16(f);
    g_Wh[i] = h;
    g_Wl[i] = __float2bfloat16(f - __bfloat162float(h));
}

// ---------------------------------------------------------------------------
// Zero the pad rows of K/V (bf16 split arrays)
// ---------------------------------------------------------------------------
__global__ void zero_pads_kernel()
{
    int i = blockIdx.x * blockDim.x + threadIdx.x;
    const int total = BATCH*HEADS * (2*WINW) * HD;
    if (i >= total) return;
    int d  = i & (HD-1);
    int t  = i >> 7;
    int jr = t & (2*WINW - 1);
    int bh = t >> 9;
    int jpad = (jr < WINW) ? jr : (S_LEN + jr);
    size_t off = ((size_t)bh*SPAD + jpad)*HD + d;
    __nv_bfloat16 z = __float2bfloat16(0.0f);
    g_Kh[off] = z; g_Kl[off] = z;
    g_Vh[off] = z; g_Vl[off] = z;
}

// ---------------------------------------------------------------------------
// Warp-MMA GEMM v2: CTA 128x128, 4 warps, warp tile 64x64 (tensor-bound:
// 32 LDSM vs 192 HMMA per warp k-tile). bf16 3-product split. K-tile 32,
// cp.async double buffer. Stage = [Ah, Al, Bh, Bl].
// ---------------------------------------------------------------------------
#define BK 32
#define NKT 32                    // 1024 / 32
#define LDSTR 40                  // smem row stride in bf16 (80 B)
#define VAR_BYTES (128*LDSTR*2)   // 10240
#define STAGE_BYTES (4*VAR_BYTES) // 40960: [Ah, Al, Bh, Bl]
#define GEMM_SMEM (2*STAGE_BYTES) // 81920

__global__ __launch_bounds__(128) void qkv_mma_kernel(
    const float* __restrict__ bq, const float* __restrict__ bk,
    const float* __restrict__ bv)
{
    extern __shared__ char smem[];
    const uint32_t smem_base = smem_to_u32(smem);
    const int tid  = threadIdx.x;
    const int wid  = tid >> 5;
    const int lane = tid & 31;

    const int col0 = blockIdx.x * 128;
    const int row0 = blockIdx.y * 128;
    const int mat  = blockIdx.z;
    const float* bia = (mat == 0) ? bq : (mat == 1 ? bk : bv);

    const __nv_bfloat16* Wh = g_Wh + (size_t)mat * 1048576;
    const __nv_bfloat16* Wl = g_Wl + (size_t)mat * 1048576;

    const __nv_bfloat16* srcs[4] = { g_Xh, g_Xl, Wh, Wl };
    const int vrow0[4] = { row0, row0, col0, col0 };

    // warp layout 2x2; warp tile 64x64
    const int warp_m0 = (wid & 1) * 64;
    const int warp_n0 = (wid >> 1) * 64;

    const int offA_row = (lane & 7) + (lane & 8);
    const int offA_k   = (lane & 16) >> 1;
    const int offB_row = (lane & 7) + ((lane & 16) >> 1);
    const int offB_k   = lane & 8;

    float acc[4][8][4];
    #pragma unroll
    for (int mt = 0; mt < 4; mt++)
        #pragma unroll
        for (int nf = 0; nf < 8; nf++)
            acc[mt][nf][0] = acc[mt][nf][1] = acc[mt][nf][2] = acc[mt][nf][3] = 0.f;

    // prefetch tile 0: 2048 16B-chunks over 128 threads = 16 each
    {
        const uint32_t sb = smem_base;
        #pragma unroll
        for (int t = 0; t < 16; t++) {
            const int i = tid + t*128;
            const int v = i >> 9, idx = i & 511;
            const int row = idx >> 2, quad = idx & 3;
            cp_async16(sb + v*VAR_BYTES + (row*LDSTR + quad*8)*2,
                       srcs[v] + (size_t)(vrow0[v] + row)*1024 + quad*8);
        }
        CP_COMMIT();
    }

    for (int kt = 0; kt < NKT; kt++) {
        if (kt + 1 < NKT) {
            const uint32_t sb = smem_base + ((kt+1) & 1) * STAGE_BYTES;
            const int k0 = (kt+1) * BK;
            #pragma unroll
            for (int t = 0; t < 16; t++) {
                const int i = tid + t*128;
                const int v = i >> 9, idx = i & 511;
                const int row = idx >> 2, quad = idx & 3;
                cp_async16(sb + v*VAR_BYTES + (row*LDSTR + quad*8)*2,
                           srcs[v] + (size_t)(vrow0[v] + row)*1024 + k0 + quad*8);
            }
            CP_COMMIT();
            CP_WAIT1();
        } else {
            CP_WAIT0();
        }
        __syncthreads();

        const uint32_t sb = smem_base + (kt & 1) * STAGE_BYTES;
        const uint32_t aH = sb, aL = sb + VAR_BYTES;
        const uint32_t bH = sb + 2*VAR_BYTES, bL = sb + 3*VAR_BYTES;

        #pragma unroll
        for (int ks = 0; ks < 2; ks++) {
            const int kk = ks * 16;
            uint32_t ahf[4][4], alf[4][4];
            #pragma unroll
            for (int mt = 0; mt < 4; mt++) {
                const uint32_t ro = (uint32_t)((warp_m0 + mt*16 + offA_row)*LDSTR
                                               + kk + offA_k) * 2;
                ldmatrix_x4(ahf[mt], aH + ro);
                ldmatrix_x4(alf[mt], aL + ro);
            }
            #pragma unroll
            for (int np = 0; np < 4; np++) {
                uint32_t bh4[4], bl4[4];
                const uint32_t ro = (uint32_t)((warp_n0 + np*16 + offB_row)*LDSTR
                                               + kk + offB_k) * 2;
                ldmatrix_x4(bh4, bH + ro);
                ldmatrix_x4(bl4, bL + ro);
                #pragma unroll
                for (int mt = 0; mt < 4; mt++) {
                    mma16816(acc[mt][2*np],   ahf[mt], &bh4[0]);
                    mma16816(acc[mt][2*np],   ahf[mt], &bl4[0]);
                    mma16816(acc[mt][2*np],   alf[mt], &bh4[0]);
                    mma16816(acc[mt][2*np+1], ahf[mt], &bh4[2]);
                    mma16816(acc[mt][2*np+1], ahf[mt], &bl4[2]);
                    mma16816(acc[mt][2*np+1], alf[mt], &bh4[2]);
                }
            }
        }
        __syncthreads();
    }

    // ---- epilogue: bias (+Q scale), split-bf16 write, view-scramble scatter ----
    const float scale = 0.08838834764831845f;   // 1/sqrt(128)
    #pragma unroll
    for (int mt = 0; mt < 4; mt++) {
        #pragma unroll
        for (int nf = 0; nf < 8; nf++) {
            const int col = col0 + warp_n0 + nf*8 + (lane & 3)*2;
            const int h   = col >> 7;
            const int dd  = col & 127;
            const float b0 = bia[col], b1 = bia[col+1];
            #pragma unroll
            for (int half_i = 0; half_i < 2; half_i++) {
                const int r  = row0 + warp_m0 + mt*16 + (lane >> 2) + half_i*8;
                const int bp = r & 1;
                const int sp = r >> 1;
                float v0 = acc[mt][nf][half_i*2+0] + b0;
                float v1 = acc[mt][nf][half_i*2+1] + b1;
                size_t idx;
                __nv_bfloat16* ah;
                __nv_bfloat16* al;
                if (mat == 0) {
                    v0 *= scale; v1 *= scale;
                    idx = ((size_t)(bp*HEADS + h)*S_LEN + sp)*HD + dd;
                    ah = g_Qh; al = g_Ql;
                } else {
                    idx = ((size_t)(bp*HEADS + h)*SPAD + (sp + WINW))*HD + dd;
                    ah = (mat == 1) ? g_Kh : g_Vh;
                    al = (mat == 1) ? g_Kl : g_Vl;
                }
                __nv_bfloat16 h0 = __float2bfloat16(v0);
                __nv_bfloat16 h1 = __float2bfloat16(v1);
                __nv_bfloat162 hv; hv.x = h0; hv.y = h1;
                __nv_bfloat162 lv;
                lv.x = __float2bfloat16(v0 - __bfloat162float(h0));
                lv.y = __float2bfloat16(v1 - __bfloat162float(h1));
                *(__nv_bfloat162*)(ah + idx) = hv;
                *(__nv_bfloat162*)(al + idx) = lv;
            }
        }
    }
}

// ---------------------------------------------------------------------------
// Banded flash attention via mma.sync (R10 structure + per-warp chunk skip):
//  - Q fragments register-cached; KV chunks double-buffered via cp.async
//  - each warp skips chunks fully outside its 16-query band (~10% less MMA)
// CTA = 128 queries of one (b',h); 8 warps x 16 queries; 10 chunks of 64 keys.
// ---------------------------------------------------------------------------
#define SSTR 136                       // smem row stride in bf16 (272 B)
#define QV_BYTES (128*SSTR*2)          // 34816 per Q var
#define KV_VAR   (64*SSTR*2)           // 17408 per KV var
#define KV_STAGE (4*KV_VAR)            // 69632: [Kh, Kl, Vh, Vl]
#define ATT_SMEM (2*QV_BYTES + 2*KV_STAGE)   // 208896

__global__ __launch_bounds__(256, 1) void attn_mma_kernel(float* __restrict__ out)
{
    extern __shared__ char smem[];
    const uint32_t sb = smem_to_u32(smem);
    const uint32_t sQh = sb, sQl = sb + QV_BYTES;
    const uint32_t sKV = sb + 2*QV_BYTES;     // two stages of [Kh,Kl,Vh,Vl]

    const int s0  = blockIdx.x * 128;
    const int h   = blockIdx.y;
    const int bp  = blockIdx.z;
    const int bh  = bp*HEADS + h;
    const int tid = threadIdx.x;
    const int wid = tid >> 5;
    const int lane = tid & 31;

    const __nv_bfloat16* Qhg = g_Qh + ((size_t)bh*S_LEN + s0)*HD;
    const __nv_bfloat16* Qlg = g_Ql + ((size_t)bh*S_LEN + s0)*HD;
    const size_t kvbase = ((size_t)bh*SPAD + s0)*HD;
    const __nv_bfloat16* gKV[4] = {
        g_Kh + kvbase, g_Kl + kvbase, g_Vh + kvbase, g_Vl + kvbase };

    // stage Q via cp.async (group 0)
    #pragma unroll
    for (int t = 0; t < 16; t++) {
        const int i = tid + t*256;          // 0..4095
        const int v = i >> 11, idx = i & 2047;
        const int row = idx >> 4, ch = idx & 15;
        cp_async16((v ? sQl : sQh) + row*272 + ch*16,
                   (v ? Qlg : Qhg) + (size_t)row*HD + ch*8);
    }
    CP_COMMIT();

    // prefetch KV chunk 0 into stage 0 (group 1)
    #pragma unroll
    for (int t = 0; t < 16; t++) {
        const int i = tid + t*256;
        const int v = i >> 10, idx = i & 1023;
        const int row = idx >> 4, ch = idx & 15;
        cp_async16(sKV + v*KV_VAR + row*272 + ch*16,
                   gKV[v] + (size_t)row*HD + ch*8);
    }
    CP_COMMIT();

    const int warp_q0 = wid * 16;
    const int offA_row = (lane & 7) + (lane & 8);
    const int offA_k   = (lane & 16) >> 1;
    const int offB_row = (lane & 7) + ((lane & 16) >> 1);
    const int offB_k   = lane & 8;
    const int vt_r = lane & 7;
    const int vt_j = ((lane >> 3) & 1) * 8;
    const int vt_d = ((lane >> 4) & 1) * 8;

    const int qlo = warp_q0 + (lane >> 2);
    const int qhi = qlo + 8;

    CP_WAIT1();            // Q ready (chunk 0 may still be in flight)
    __syncthreads();

    // cache Q fragments in registers for all 8 k-steps
    uint32_t qh[8][4], ql[8][4];
    #pragma unroll
    for (int ks = 0; ks < 8; ks++) {
        const uint32_t qo = (uint32_t)((warp_q0 + offA_row)*SSTR
                                       + ks*16 + offA_k) * 2;
        ldmatrix_x4(qh[ks], sQh + qo);
        ldmatrix_x4(ql[ks], sQl + qo);
    }

    float of[16][4];
    #pragma unroll
    for (int f = 0; f < 16; f++)
        of[f][0] = of[f][1] = of[f][2] = of[f][3] = 0.f;
    float m_lo = -1e30f, m_hi = -1e30f, l_lo = 0.f, l_hi = 0.f;

    for (int c = 0; c < 10; c++) {
        // prefetch chunk c+1 into the other stage
        if (c < 9) {
            const uint32_t dstS = sKV + ((c+1) & 1) * KV_STAGE;
            const size_t srcOff = (size_t)(c+1)*64*HD;
            #pragma unroll
            for (int t = 0; t < 16; t++) {
                const int i = tid + t*256;
                const int v = i >> 10, idx = i & 1023;
                const int row = idx >> 4, ch = idx & 15;
                cp_async16(dstS + v*KV_VAR + row*272 + ch*16,
                           gKV[v] + srcOff + (size_t)row*HD + ch*8);
            }
            CP_COMMIT();
            CP_WAIT1();        // chunk c complete
        } else {
            CP_WAIT0();
        }
        __syncthreads();

        // per-warp band test: chunk keys [c*64, c*64+63] vs band
        // [warp_q0, warp_q0+15+512] (uniform across the warp)
        const bool active = (c*64 + 63 >= warp_q0) && (c*64 <= warp_q0 + 527);
        if (active) {
            const uint32_t stg = sKV + (c & 1) * KV_STAGE;
            const uint32_t cKh = stg, cKl = stg + KV_VAR;
            const uint32_t cVh = stg + 2*KV_VAR, cVl = stg + 3*KV_VAR;

            // ---- S = Q K^T (64 keys), split-bf16, fp32 accum ----
            float sf[8][4];
            #pragma unroll
            for (int f = 0; f < 8; f++)
                sf[f][0] = sf[f][1] = sf[f][2] = sf[f][3] = 0.f;

            #pragma unroll
            for (int ks = 0; ks < 8; ks++) {
                #pragma unroll
                for (int ng = 0; ng < 4; ng++) {
                    uint32_t kh4[4], kl4[4];
                    const uint32_t ko = (uint32_t)((ng*16 + offB_row)*SSTR
                                                   + ks*16 + offB_k) * 2;
                    ldmatrix_x4(kh4, cKh + ko);
                    ldmatrix_x4(kl4, cKl + ko);
                    mma16816(sf[2*ng],   qh[ks], &kh4[0]);
                    mma16816(sf[2*ng],   qh[ks], &kl4[0]);
                    mma16816(sf[2*ng],   ql[ks], &kh4[0]);
                    mma16816(sf[2*ng+1], qh[ks], &kh4[2]);
                    mma16816(sf[2*ng+1], qh[ks], &kl4[2]);
                    mma16816(sf[2*ng+1], ql[ks], &kh4[2]);
                }
            }

            // ---- masked online softmax ----
            const int kb = c*64 + (lane & 3)*2;
            float mxlo = -1e30f, mxhi = -1e30f;
            #pragma unroll
            for (int f = 0; f < 8; f++) {
                #pragma unroll
                for (int j = 0; j < 2; j++) {
                    const int kc = kb + f*8 + j;
                    const bool vlo = (kc >= qlo) && (kc <= qlo + 512);
                    const bool vhi = (kc >= qhi) && (kc <= qhi + 512);
                    const float slo = vlo ? sf[f][j]   : -1e30f;
                    const float shi = vhi ? sf[f][2+j] : -1e30f;
                    sf[f][j]   = slo;  mxlo = fmaxf(mxlo, slo);
                    sf[f][2+j] = shi;  mxhi = fmaxf(mxhi, shi);
                }
            }
            mxlo = fmaxf(mxlo, __shfl_xor_sync(0xffffffffu, mxlo, 1));
            mxlo = fmaxf(mxlo, __shfl_xor_sync(0xffffffffu, mxlo, 2));
            mxhi = fmaxf(mxhi, __shfl_xor_sync(0xffffffffu, mxhi, 1));
            mxhi = fmaxf(mxhi, __shfl_xor_sync(0xffffffffu, mxhi, 2));

            const float mnlo = fmaxf(m_lo, mxlo);
            const float mnhi = fmaxf(m_hi, mxhi);
            const float alo = __expf(m_lo - mnlo);
            const float ahi = __expf(m_hi - mnhi);
            m_lo = mnlo; m_hi = mnhi;

            float sumlo = 0.f, sumhi = 0.f;
            #pragma unroll
            for (int f = 0; f < 8; f++) {
                #pragma unroll
                for (int j = 0; j < 2; j++) {
                    const int kc = kb + f*8 + j;
                    const bool vlo = (kc >= qlo) && (kc <= qlo + 512);
                    const bool vhi = (kc >= qhi) && (kc <= qhi + 512);
                    const float plo = vlo ? __expf(sf[f][j]   - mnlo) : 0.f;
                    const float phi = vhi ? __expf(sf[f][2+j] - mnhi) : 0.f;
                    sf[f][j] = plo;   sumlo += plo;
                    sf[f][2+j] = phi; sumhi += phi;
                }
            }
            sumlo += __shfl_xor_sync(0xffffffffu, sumlo, 1);
            sumlo += __shfl_xor_sync(0xffffffffu, sumlo, 2);
            sumhi += __shfl_xor_sync(0xffffffffu, sumhi, 1);
            sumhi += __shfl_xor_sync(0xffffffffu, sumhi, 2);
            l_lo = l_lo*alo + sumlo;
            l_hi = l_hi*ahi + sumhi;

            #pragma unroll
            for (int f = 0; f < 16; f++) {
                of[f][0] *= alo; of[f][1] *= alo;
                of[f][2] *= ahi; of[f][3] *= ahi;
            }

            // ---- O += P V, split-bf16 ----
            #pragma unroll
            for (int t = 0; t < 4; t++) {
                uint32_t ah[4], al[4];
                #pragma unroll
                for (int g = 0; g < 4; g++) {
                    const int fr = 2*t + (g >> 1);
                    const int b0 = (g & 1) * 2;
                    const float p0 = sf[fr][b0], p1 = sf[fr][b0+1];
                    const float h0 = __bfloat162float(__float2bfloat16(p0));
                    const float h1 = __bfloat162float(__float2bfloat16(p1));
                    ah[g] = pack_bf16x2(h0, h1);
                    al[g] = pack_bf16x2(p0 - h0, p1 - h1);
                }
                #pragma unroll
                for (int dg = 0; dg < 8; dg++) {
                    uint32_t vh4[4], vl4[4];
                    const uint32_t vo = (uint32_t)((t*16 + vt_j + vt_r)*SSTR
                                                   + dg*16 + vt_d) * 2;
                    ldmatrix_x4_trans(vh4, cVh + vo);
                    ldmatrix_x4_trans(vl4, cVl + vo);
                    mma16816(of[2*dg],   ah, &vh4[0]);
                    mma16816(of[2*dg],   ah, &vl4[0]);
                    mma16816(of[2*dg],   al, &vh4[0]);
                    mma16816(of[2*dg+1], ah, &vh4[2]);
                    mma16816(of[2*dg+1], ah, &vl4[2]);
                    mma16816(of[2*dg+1], al, &vh4[2]);
                }
            }
        }
        __syncthreads();
    }

    // ---- write out: out[s'][b'][h*128+d] ----
    const float invlo = 1.f / l_lo;
    const float invhi = 1.f / l_hi;
    const int sqlo = s0 + qlo;
    const int sqhi = s0 + qhi;
    const size_t obase = (size_t)bp*1024 + h*128 + (lane & 3)*2;
    #pragma unroll
    for (int f = 0; f < 16; f++) {
        const int d = f*8;
        float2 o1; o1.x = of[f][0]*invlo; o1.y = of[f][1]*invlo;
        *(float2*)&out[(size_t)sqlo*2048 + obase + d] = o1;
        float2 o2; o2.x = of[f][2]*invhi; o2.y = of[f][3]*invhi;
        *(float2*)&out[(size_t)sqhi*2048 + obase + d] = o2;
    }
}

// ---------------------------------------------------------------------------
extern "C" void kernel_launch(void* const* d_in, const int* in_sizes, int n_in,
                              void* d_out, int out_size)
{
    (void)in_sizes; (void)n_in; (void)out_size;
    const float* val = (const float*)d_in[0];
    const float* Wq  = (const float*)d_in[1];
    const float* bq  = (const float*)d_in[2];
    const float* Wk  = (const float*)d_in[3];
    const float* bk  = (const float*)d_in[4];
    const float* Wv  = (const float*)d_in[5];
    const float* bv  = (const float*)d_in[6];
    float* out = (float*)d_out;

    cudaFuncSetAttribute(qkv_mma_kernel, cudaFuncAttributeMaxDynamicSharedMemorySize,
                         GEMM_SMEM);
    cudaFuncSetAttribute(attn_mma_kernel, cudaFuncAttributeMaxDynamicSharedMemorySize,
                         ATT_SMEM);

    convert_x_kernel<<<(8192*1024)/256, 256>>>(val);
    convert_w_kernel<<<(3*1024*1024)/256, 256>>>(Wq, Wk, Wv);
    {
        const int total = BATCH*HEADS * (2*WINW) * HD;
        zero_pads_kernel<<<(total + 255)/256, 256>>>();
    }
    {
        dim3 grid(1024/128, 8192/128, 3);
        qkv_mma_kernel<<<grid, 128, GEMM_SMEM>>>(bq, bk, bv);
    }
    {
        dim3 grid(S_LEN/128, HEADS, BATCH);
        attn_mma_kernel<<<grid, 256, ATT_SMEM>>>(out);
    }
}

// round 15
// speedup vs baseline: 1.1776x; 1.0101x over previous
#include <cuda_runtime.h>
#include <cuda_bf16.h>
#include <cstdint>
#include <cstddef>

#define S_LEN 4096
#define BATCH 2
#define EMB   1024
#define HEADS 8
#define HD    128
#define WINW  256
#define SPAD  (S_LEN + 2*WINW)   // 4608

// Split-bf16 Q/K/V in attention layout (written by GEMM epilogue)
__device__ __align__(16) __nv_bfloat16 g_Qh[BATCH*HEADS*S_LEN*HD];
__device__ __align__(16) __nv_bfloat16 g_Ql[BATCH*HEADS*S_LEN*HD];
__device__ __align__(16) __nv_bfloat16 g_Kh[BATCH*HEADS*SPAD*HD];
__device__ __align__(16) __nv_bfloat16 g_Kl[BATCH*HEADS*SPAD*HD];
__device__ __align__(16) __nv_bfloat16 g_Vh[BATCH*HEADS*SPAD*HD];
__device__ __align__(16) __nv_bfloat16 g_Vl[BATCH*HEADS*SPAD*HD];

// Split-bf16 GEMM inputs
__device__ __align__(16) __nv_bfloat16 g_Xh[8192*1024];
__device__ __align__(16) __nv_bfloat16 g_Xl[8192*1024];
__device__ __align__(16) __nv_bfloat16 g_Wh[3*1024*1024];
__device__ __align__(16) __nv_bfloat16 g_Wl[3*1024*1024];

// ---------------------------------------------------------------------------
// helpers
// ---------------------------------------------------------------------------
__device__ __forceinline__ uint32_t smem_to_u32(const void* p) {
    uint32_t a;
    asm("{ .reg .u64 t; cvta.to.shared.u64 t, %1; cvt.u32.u64 %0, t; }"
        : "=r"(a) : "l"(p));
    return a;
}
__device__ __forceinline__ void cp_async16(uint32_t dst, const void* src) {
    asm volatile("cp.async.cg.shared.global [%0], [%1], 16;"
                 :: "r"(dst), "l"(src) : "memory");
}
#define CP_COMMIT() asm volatile("cp.async.commit_group;" ::: "memory")
#define CP_WAIT0()  asm volatile("cp.async.wait_group 0;" ::: "memory")
#define CP_WAIT1()  asm volatile("cp.async.wait_group 1;" ::: "memory")

__device__ __forceinline__ void ldmatrix_x4(uint32_t* r, uint32_t addr) {
    asm volatile("ldmatrix.sync.aligned.m8n8.x4.shared.b16 {%0,%1,%2,%3}, [%4];"
                 : "=r"(r[0]), "=r"(r[1]), "=r"(r[2]), "=r"(r[3]) : "r"(addr));
}
__device__ __forceinline__ void ldmatrix_x4_trans(uint32_t* r, uint32_t addr) {
    asm volatile("ldmatrix.sync.aligned.m8n8.x4.trans.shared.b16 {%0,%1,%2,%3}, [%4];"
                 : "=r"(r[0]), "=r"(r[1]), "=r"(r[2]), "=r"(r[3]) : "r"(addr));
}
__device__ __forceinline__ void mma16816(float* c, const uint32_t* a,
                                         const uint32_t* b) {
    asm volatile(
        "mma.sync.aligned.m16n8k16.row.col.f32.bf16.bf16.f32 "
        "{%0,%1,%2,%3}, {%4,%5,%6,%7}, {%8,%9}, {%0,%1,%2,%3};"
        : "+f"(c[0]), "+f"(c[1]), "+f"(c[2]), "+f"(c[3])
        : "r"(a[0]), "r"(a[1]), "r"(a[2]), "r"(a[3]), "r"(b[0]), "r"(b[1]));
}
__device__ __forceinline__ uint32_t pack_bf16x2(float lo, float hi) {
    uint32_t r;
    asm("cvt.rn.bf16x2.f32 %0, %1, %2;" : "=r"(r) : "f"(hi), "f"(lo));
    return r;
}

// ---------------------------------------------------------------------------
// Split fp32 -> (bf16 hi, bf16 lo). X rows are the view-scramble gather.
// ---------------------------------------------------------------------------
__global__ void convert_x_kernel(const float* __restrict__ val)
{
    int i = blockIdx.x * blockDim.x + threadIdx.x;
    if (i >= 8192*1024) return;
    int r = i >> 10, k = i & 1023;
    int b = r >> 12, s = r & 4095;
    float f = val[s*2048 + b*1024 + k];
    __nv_bfloat16 h = __float2bfloat16(f);
    g_Xh[i] = h;
    g_Xl[i] = __float2bfloat16(f - __bfloat162float(h));
}

__global__ void convert_w_kernel(const float* __restrict__ Wq,
                                 const float* __restrict__ Wk,
                                 const float* __restrict__ Wv)
{
    int i = blockIdx.x * blockDim.x + threadIdx.x;
    if (i >= 3*1024*1024) return;
    int mat = i >> 20;
    const float* W = (mat == 0) ? Wq : (mat == 1 ? Wk : Wv);
    float f = W[i & 0xFFFFF];
    __nv_bfloat16 h = __float2bfloat16(f);
    g_Wh[i] = h;
    g_Wl[i] = __float2bfloat16(f - __bfloat162float(h));
}

// ---------------------------------------------------------------------------
// Zero the pad rows of K/V (bf16 split arrays)
// ---------------------------------------------------------------------------
__global__ void zero_pads_kernel()
{
    int i = blockIdx.x * blockDim.x + threadIdx.x;
    const int total = BATCH*HEADS * (2*WINW) * HD;
    if (i >= total) return;
    int d  = i & (HD-1);
    int t  = i >> 7;
    int jr = t & (2*WINW - 1);
    int bh = t >> 9;
    int jpad = (jr < WINW) ? jr : (S_LEN + jr);
    size_t off = ((size_t)bh*SPAD + jpad)*HD + d;
    __nv_bfloat16 z = __float2bfloat16(0.0f);
    g_Kh[off] = z; g_Kl[off] = z;
    g_Vh[off] = z; g_Vl[off] = z;
}

// ---------------------------------------------------------------------------
// Warp-MMA GEMM v3: CTA 128x128, 4 warps, warp tile 64x64. bf16 3-product
// split issued in product-major passes so consecutive MMAs never share an
// accumulator (same-acc reuse distance 32). K-tile 32, cp.async double buffer.
// ---------------------------------------------------------------------------
#define BK 32
#define NKT 32                    // 1024 / 32
#define LDSTR 40                  // smem row stride in bf16 (80 B)
#define VAR_BYTES (128*LDSTR*2)   // 10240
#define STAGE_BYTES (4*VAR_BYTES) // 40960: [Ah, Al, Bh, Bl]
#define GEMM_SMEM (2*STAGE_BYTES) // 81920

__global__ __launch_bounds__(128) void qkv_mma_kernel(
    const float* __restrict__ bq, const float* __restrict__ bk,
    const float* __restrict__ bv)
{
    extern __shared__ char smem[];
    const uint32_t smem_base = smem_to_u32(smem);
    const int tid  = threadIdx.x;
    const int wid  = tid >> 5;
    const int lane = tid & 31;

    const int col0 = blockIdx.x * 128;
    const int row0 = blockIdx.y * 128;
    const int mat  = blockIdx.z;
    const float* bia = (mat == 0) ? bq : (mat == 1 ? bk : bv);

    const __nv_bfloat16* Wh = g_Wh + (size_t)mat * 1048576;
    const __nv_bfloat16* Wl = g_Wl + (size_t)mat * 1048576;

    const __nv_bfloat16* srcs[4] = { g_Xh, g_Xl, Wh, Wl };
    const int vrow0[4] = { row0, row0, col0, col0 };

    // warp layout 2x2; warp tile 64x64
    const int warp_m0 = (wid & 1) * 64;
    const int warp_n0 = (wid >> 1) * 64;

    const int offA_row = (lane & 7) + (lane & 8);
    const int offA_k   = (lane & 16) >> 1;
    const int offB_row = (lane & 7) + ((lane & 16) >> 1);
    const int offB_k   = lane & 8;

    float acc[4][8][4];
    #pragma unroll
    for (int mt = 0; mt < 4; mt++)
        #pragma unroll
        for (int nf = 0; nf < 8; nf++)
            acc[mt][nf][0] = acc[mt][nf][1] = acc[mt][nf][2] = acc[mt][nf][3] = 0.f;

    // prefetch tile 0: 2048 16B-chunks over 128 threads = 16 each
    {
        const uint32_t sb = smem_base;
        #pragma unroll
        for (int t = 0; t < 16; t++) {
            const int i = tid + t*128;
            const int v = i >> 9, idx = i & 511;
            const int row = idx >> 2, quad = idx & 3;
            cp_async16(sb + v*VAR_BYTES + (row*LDSTR + quad*8)*2,
                       srcs[v] + (size_t)(vrow0[v] + row)*1024 + quad*8);
        }
        CP_COMMIT();
    }

    for (int kt = 0; kt < NKT; kt++) {
        if (kt + 1 < NKT) {
            const uint32_t sb = smem_base + ((kt+1) & 1) * STAGE_BYTES;
            const int k0 = (kt+1) * BK;
            #pragma unroll
            for (int t = 0; t < 16; t++) {
                const int i = tid + t*128;
                const int v = i >> 9, idx = i & 511;
                const int row = idx >> 2, quad = idx & 3;
                cp_async16(sb + v*VAR_BYTES + (row*LDSTR + quad*8)*2,
                           srcs[v] + (size_t)(vrow0[v] + row)*1024 + k0 + quad*8);
            }
            CP_COMMIT();
            CP_WAIT1();
        } else {
            CP_WAIT0();
        }
        __syncthreads();

        const uint32_t sb = smem_base + (kt & 1) * STAGE_BYTES;
        const uint32_t aH = sb, aL = sb + VAR_BYTES;
        const uint32_t bH = sb + 2*VAR_BYTES, bL = sb + 3*VAR_BYTES;

        #pragma unroll
        for (int ks = 0; ks < 2; ks++) {
            const int kk = ks * 16;
            // load ALL fragments for this k-step first
            uint32_t ahf[4][4], alf[4][4], bh4[4][4], bl4[4][4];
            #pragma unroll
            for (int mt = 0; mt < 4; mt++) {
                const uint32_t ro = (uint32_t)((warp_m0 + mt*16 + offA_row)*LDSTR
                                               + kk + offA_k) * 2;
                ldmatrix_x4(ahf[mt], aH + ro);
                ldmatrix_x4(alf[mt], aL + ro);
            }
            #pragma unroll
            for (int np = 0; np < 4; np++) {
                const uint32_t ro = (uint32_t)((warp_n0 + np*16 + offB_row)*LDSTR
                                               + kk + offB_k) * 2;
                ldmatrix_x4(bh4[np], bH + ro);
                ldmatrix_x4(bl4[np], bL + ro);
            }
            // product-major passes: consecutive MMAs hit distinct accumulators
            #pragma unroll
            for (int np = 0; np < 4; np++)
                #pragma unroll
                for (int mt = 0; mt < 4; mt++) {
                    mma16816(acc[mt][2*np],   ahf[mt], &bh4[np][0]);
                    mma16816(acc[mt][2*np+1], ahf[mt], &bh4[np][2]);
                }
            #pragma unroll
            for (int np = 0; np < 4; np++)
                #pragma unroll
                for (int mt = 0; mt < 4; mt++) {
                    mma16816(acc[mt][2*np],   ahf[mt], &bl4[np][0]);
                    mma16816(acc[mt][2*np+1], ahf[mt], &bl4[np][2]);
                }
            #pragma unroll
            for (int np = 0; np < 4; np++)
                #pragma unroll
                for (int mt = 0; mt < 4; mt++) {
                    mma16816(acc[mt][2*np],   alf[mt], &bh4[np][0]);
                    mma16816(acc[mt][2*np+1], alf[mt], &bh4[np][2]);
                }
        }
        __syncthreads();
    }

    // ---- epilogue: bias (+Q scale), split-bf16 write, view-scramble scatter ----
    const float scale = 0.08838834764831845f;   // 1/sqrt(128)
    #pragma unroll
    for (int mt = 0; mt < 4; mt++) {
        #pragma unroll
        for (int nf = 0; nf < 8; nf++) {
            const int col = col0 + warp_n0 + nf*8 + (lane & 3)*2;
            const int h   = col >> 7;
            const int dd  = col & 127;
            const float b0 = bia[col], b1 = bia[col+1];
            #pragma unroll
            for (int half_i = 0; half_i < 2; half_i++) {
                const int r  = row0 + warp_m0 + mt*16 + (lane >> 2) + half_i*8;
                const int bp = r & 1;
                const int sp = r >> 1;
                float v0 = acc[mt][nf][half_i*2+0] + b0;
                float v1 = acc[mt][nf][half_i*2+1] + b1;
                size_t idx;
                __nv_bfloat16* ah;
                __nv_bfloat16* al;
                if (mat == 0) {
                    v0 *= scale; v1 *= scale;
                    idx = ((size_t)(bp*HEADS + h)*S_LEN + sp)*HD + dd;
                    ah = g_Qh; al = g_Ql;
                } else {
                    idx = ((size_t)(bp*HEADS + h)*SPAD + (sp + WINW))*HD + dd;
                    ah = (mat == 1) ? g_Kh : g_Vh;
                    al = (mat == 1) ? g_Kl : g_Vl;
                }
                __nv_bfloat16 h0 = __float2bfloat16(v0);
                __nv_bfloat16 h1 = __float2bfloat16(v1);
                __nv_bfloat162 hv; hv.x = h0; hv.y = h1;
                __nv_bfloat162 lv;
                lv.x = __float2bfloat16(v0 - __bfloat162float(h0));
                lv.y = __float2bfloat16(v1 - __bfloat162float(h1));
                *(__nv_bfloat162*)(ah + idx) = hv;
                *(__nv_bfloat162*)(al + idx) = lv;
            }
        }
    }
}

// ---------------------------------------------------------------------------
// Banded flash attention via mma.sync (chunk-skip + dependency-spread MMAs):
//  - Q fragments register-cached; KV chunks double-buffered via cp.async
//  - QK and PV issue split products in passes over fragment pairs so the
//    same accumulator repeats at distance 4 instead of 1
// CTA = 128 queries of one (b',h); 8 warps x 16 queries; 10 chunks of 64 keys.
// ---------------------------------------------------------------------------
#define SSTR 136                       // smem row stride in bf16 (272 B)
#define QV_BYTES (128*SSTR*2)          // 34816 per Q var
#define KV_VAR   (64*SSTR*2)           // 17408 per KV var
#define KV_STAGE (4*KV_VAR)            // 69632: [Kh, Kl, Vh, Vl]
#define ATT_SMEM (2*QV_BYTES + 2*KV_STAGE)   // 208896

__global__ __launch_bounds__(256, 1) void attn_mma_kernel(float* __restrict__ out)
{
    extern __shared__ char smem[];
    const uint32_t sb = smem_to_u32(smem);
    const uint32_t sQh = sb, sQl = sb + QV_BYTES;
    const uint32_t sKV = sb + 2*QV_BYTES;     // two stages of [Kh,Kl,Vh,Vl]

    const int s0  = blockIdx.x * 128;
    const int h   = blockIdx.y;
    const int bp  = blockIdx.z;
    const int bh  = bp*HEADS + h;
    const int tid = threadIdx.x;
    const int wid = tid >> 5;
    const int lane = tid & 31;

    const __nv_bfloat16* Qhg = g_Qh + ((size_t)bh*S_LEN + s0)*HD;
    const __nv_bfloat16* Qlg = g_Ql + ((size_t)bh*S_LEN + s0)*HD;
    const size_t kvbase = ((size_t)bh*SPAD + s0)*HD;
    const __nv_bfloat16* gKV[4] = {
        g_Kh + kvbase, g_Kl + kvbase, g_Vh + kvbase, g_Vl + kvbase };

    // stage Q via cp.async (group 0)
    #pragma unroll
    for (int t = 0; t < 16; t++) {
        const int i = tid + t*256;          // 0..4095
        const int v = i >> 11, idx = i & 2047;
        const int row = idx >> 4, ch = idx & 15;
        cp_async16((v ? sQl : sQh) + row*272 + ch*16,
                   (v ? Qlg : Qhg) + (size_t)row*HD + ch*8);
    }
    CP_COMMIT();

    // prefetch KV chunk 0 into stage 0 (group 1)
    #pragma unroll
    for (int t = 0; t < 16; t++) {
        const int i = tid + t*256;
        const int v = i >> 10, idx = i & 1023;
        const int row = idx >> 4, ch = idx & 15;
        cp_async16(sKV + v*KV_VAR + row*272 + ch*16,
                   gKV[v] + (size_t)row*HD + ch*8);
    }
    CP_COMMIT();

    const int warp_q0 = wid * 16;
    const int offA_row = (lane & 7) + (lane & 8);
    const int offA_k   = (lane & 16) >> 1;
    const int offB_row = (lane & 7) + ((lane & 16) >> 1);
    const int offB_k   = lane & 8;
    const int vt_r = lane & 7;
    const int vt_j = ((lane >> 3) & 1) * 8;
    const int vt_d = ((lane >> 4) & 1) * 8;

    const int qlo = warp_q0 + (lane >> 2);
    const int qhi = qlo + 8;

    CP_WAIT1();            // Q ready (chunk 0 may still be in flight)
    __syncthreads();

    // cache Q fragments in registers for all 8 k-steps
    uint32_t qh[8][4], ql[8][4];
    #pragma unroll
    for (int ks = 0; ks < 8; ks++) {
        const uint32_t qo = (uint32_t)((warp_q0 + offA_row)*SSTR
                                       + ks*16 + offA_k) * 2;
        ldmatrix_x4(qh[ks], sQh + qo);
        ldmatrix_x4(ql[ks], sQl + qo);
    }

    float of[16][4];
    #pragma unroll
    for (int f = 0; f < 16; f++)
        of[f][0] = of[f][1] = of[f][2] = of[f][3] = 0.f;
    float m_lo = -1e30f, m_hi = -1e30f, l_lo = 0.f, l_hi = 0.f;

    for (int c = 0; c < 10; c++) {
        // prefetch chunk c+1 into the other stage
        if (c < 9) {
            const uint32_t dstS = sKV + ((c+1) & 1) * KV_STAGE;
            const size_t srcOff = (size_t)(c+1)*64*HD;
            #pragma unroll
            for (int t = 0; t < 16; t++) {
                const int i = tid + t*256;
                const int v = i >> 10, idx = i & 1023;
                const int row = idx >> 4, ch = idx & 15;
                cp_async16(dstS + v*KV_VAR + row*272 + ch*16,
                           gKV[v] + srcOff + (size_t)row*HD + ch*8);
            }
            CP_COMMIT();
            CP_WAIT1();        // chunk c complete
        } else {
            CP_WAIT0();
        }
        __syncthreads();

        // per-warp band test (uniform across the warp)
        const bool active = (c*64 + 63 >= warp_q0) && (c*64 <= warp_q0 + 527);
        if (active) {
            const uint32_t stg = sKV + (c & 1) * KV_STAGE;
            const uint32_t cKh = stg, cKl = stg + KV_VAR;
            const uint32_t cVh = stg + 2*KV_VAR, cVl = stg + 3*KV_VAR;

            // ---- S = Q K^T (64 keys), split-bf16, fp32 accum ----
            float sf[8][4];
            #pragma unroll
            for (int f = 0; f < 8; f++)
                sf[f][0] = sf[f][1] = sf[f][2] = sf[f][3] = 0.f;

            #pragma unroll
            for (int ks = 0; ks < 8; ks++) {
                #pragma unroll
                for (int ng2 = 0; ng2 < 2; ng2++) {
                    // load K fragments for ng = 2*ng2, 2*ng2+1
                    uint32_t kh4[2][4], kl4[2][4];
                    #pragma unroll
                    for (int s = 0; s < 2; s++) {
                        const int ng = 2*ng2 + s;
                        const uint32_t ko = (uint32_t)((ng*16 + offB_row)*SSTR
                                                       + ks*16 + offB_k) * 2;
                        ldmatrix_x4(kh4[s], cKh + ko);
                        ldmatrix_x4(kl4[s], cKl + ko);
                    }
                    // product-major passes, distance-4 accumulator reuse
                    #pragma unroll
                    for (int s = 0; s < 2; s++) {
                        const int ng = 2*ng2 + s;
                        mma16816(sf[2*ng],   qh[ks], &kh4[s][0]);
                        mma16816(sf[2*ng+1], qh[ks], &kh4[s][2]);
                    }
                    #pragma unroll
                    for (int s = 0; s < 2; s++) {
                        const int ng = 2*ng2 + s;
                        mma16816(sf[2*ng],   qh[ks], &kl4[s][0]);
                        mma16816(sf[2*ng+1], qh[ks], &kl4[s][2]);
                    }
                    #pragma unroll
                    for (int s = 0; s < 2; s++) {
                        const int ng = 2*ng2 + s;
                        mma16816(sf[2*ng],   ql[ks], &kh4[s][0]);
                        mma16816(sf[2*ng+1], ql[ks], &kh4[s][2]);
                    }
                }
            }

            // ---- masked online softmax ----
            const int kb = c*64 + (lane & 3)*2;
            float mxlo = -1e30f, mxhi = -1e30f;
            #pragma unroll
            for (int f = 0; f < 8; f++) {
                #pragma unroll
                for (int j = 0; j < 2; j++) {
                    const int kc = kb + f*8 + j;
                    const bool vlo = (kc >= qlo) && (kc <= qlo + 512);
                    const bool vhi = (kc >= qhi) && (kc <= qhi + 512);
                    const float slo = vlo ? sf[f][j]   : -1e30f;
                    const float shi = vhi ? sf[f][2+j] : -1e30f;
                    sf[f][j]   = slo;  mxlo = fmaxf(mxlo, slo);
                    sf[f][2+j] = shi;  mxhi = fmaxf(mxhi, shi);
                }
            }
            mxlo = fmaxf(mxlo, __shfl_xor_sync(0xffffffffu, mxlo, 1));
            mxlo = fmaxf(mxlo, __shfl_xor_sync(0xffffffffu, mxlo, 2));
            mxhi = fmaxf(mxhi, __shfl_xor_sync(0xffffffffu, mxhi, 1));
            mxhi = fmaxf(mxhi, __shfl_xor_sync(0xffffffffu, mxhi, 2));

            const float mnlo = fmaxf(m_lo, mxlo);
            const float mnhi = fmaxf(m_hi, mxhi);
            const float alo = __expf(m_lo - mnlo);
            const float ahi = __expf(m_hi - mnhi);
            m_lo = mnlo; m_hi = mnhi;

            float sumlo = 0.f, sumhi = 0.f;
            #pragma unroll
            for (int f = 0; f < 8; f++) {
                #pragma unroll
                for (int j = 0; j < 2; j++) {
                    const int kc = kb + f*8 + j;
                    const bool vlo = (kc >= qlo) && (kc <= qlo + 512);
                    const bool vhi = (kc >= qhi) && (kc <= qhi + 512);
                    const float plo = vlo ? __expf(sf[f][j]   - mnlo) : 0.f;
                    const float phi = vhi ? __expf(sf[f][2+j] - mnhi) : 0.f;
                    sf[f][j] = plo;   sumlo += plo;
                    sf[f][2+j] = phi; sumhi += phi;
                }
            }
            sumlo += __shfl_xor_sync(0xffffffffu, sumlo, 1);
            sumlo += __shfl_xor_sync(0xffffffffu, sumlo, 2);
            sumhi += __shfl_xor_sync(0xffffffffu, sumhi, 1);
            sumhi += __shfl_xor_sync(0xffffffffu, sumhi, 2);
            l_lo = l_lo*alo + sumlo;
            l_hi = l_hi*ahi + sumhi;

            #pragma unroll
            for (int f = 0; f < 16; f++) {
                of[f][0] *= alo; of[f][1] *= alo;
                of[f][2] *= ahi; of[f][3] *= ahi;
            }

            // ---- O += P V, split-bf16, distance-4 accumulator reuse ----
            #pragma unroll
            for (int t = 0; t < 4; t++) {
                uint32_t ah[4], al[4];
                #pragma unroll
                for (int g = 0; g < 4; g++) {
                    const int fr = 2*t + (g >> 1);
                    const int b0 = (g & 1) * 2;
                    const float p0 = sf[fr][b0], p1 = sf[fr][b0+1];
                    const float h0 = __bfloat162float(__float2bfloat16(p0));
                    const float h1 = __bfloat162float(__float2bfloat16(p1));
                    ah[g] = pack_bf16x2(h0, h1);
                    al[g] = pack_bf16x2(p0 - h0, p1 - h1);
                }
                #pragma unroll
                for (int dg2 = 0; dg2 < 4; dg2++) {
                    uint32_t vh4[2][4], vl4[2][4];
                    #pragma unroll
                    for (int s = 0; s < 2; s++) {
                        const int dg = 2*dg2 + s;
                        const uint32_t vo = (uint32_t)((t*16 + vt_j + vt_r)*SSTR
                                                       + dg*16 + vt_d) * 2;
                        ldmatrix_x4_trans(vh4[s], cVh + vo);
                        ldmatrix_x4_trans(vl4[s], cVl + vo);
                    }
                    #pragma unroll
                    for (int s = 0; s < 2; s++) {
                        const int dg = 2*dg2 + s;
                        mma16816(of[2*dg],   ah, &vh4[s][0]);
                        mma16816(of[2*dg+1], ah, &vh4[s][2]);
                    }
                    #pragma unroll
                    for (int s = 0; s < 2; s++) {
                        const int dg = 2*dg2 + s;
                        mma16816(of[2*dg],   ah, &vl4[s][0]);
                        mma16816(of[2*dg+1], ah, &vl4[s][2]);
                    }
                    #pragma unroll
                    for (int s = 0; s < 2; s++) {
                        const int dg = 2*dg2 + s;
                        mma16816(of[2*dg],   al, &vh4[s][0]);
                        mma16816(of[2*dg+1], al, &vh4[s][2]);
                    }
                }
            }
        }
        __syncthreads();
    }

    // ---- write out: out[s'][b'][h*128+d] ----
    const float invlo = 1.f / l_lo;
    const float invhi = 1.f / l_hi;
    const int sqlo = s0 + qlo;
    const int sqhi = s0 + qhi;
    const size_t obase = (size_t)bp*1024 + h*128 + (lane & 3)*2;
    #pragma unroll
    for (int f = 0; f < 16; f++) {
        const int d = f*8;
        float2 o1; o1.x = of[f][0]*invlo; o1.y = of[f][1]*invlo;
        *(float2*)&out[(size_t)sqlo*2048 + obase + d] = o1;
        float2 o2; o2.x = of[f][2]*invhi; o2.y = of[f][3]*invhi;
        *(float2*)&out[(size_t)sqhi*2048 + obase + d] = o2;
    }
}

// ---------------------------------------------------------------------------
extern "C" void kernel_launch(void* const* d_in, const int* in_sizes, int n_in,
                              void* d_out, int out_size)
{
    (void)in_sizes; (void)n_in; (void)out_size;
    const float* val = (const float*)d_in[0];
    const float* Wq  = (const float*)d_in[1];
    const float* bq  = (const float*)d_in[2];
    const float* Wk  = (const float*)d_in[3];
    const float* bk  = (const float*)d_in[4];
    const float* Wv  = (const float*)d_in[5];
    const float* bv  = (const float*)d_in[6];
    float* out = (float*)d_out;

    cudaFuncSetAttribute(qkv_mma_kernel, cudaFuncAttributeMaxDynamicSharedMemorySize,
                         GEMM_SMEM);
    cudaFuncSetAttribute(attn_mma_kernel, cudaFuncAttributeMaxDynamicSharedMemorySize,
                         ATT_SMEM);

    convert_x_kernel<<<(8192*1024)/256, 256>>>(val);
    convert_w_kernel<<<(3*1024*1024)/256, 256>>>(Wq, Wk, Wv);
    {
        const int total = BATCH*HEADS * (2*WINW) * HD;
        zero_pads_kernel<<<(total + 255)/256, 256>>>();
    }
    {
        dim3 grid(1024/128, 8192/128, 3);
        qkv_mma_kernel<<<grid, 128, GEMM_SMEM>>>(bq, bk, bv);
    }
    {
        dim3 grid(S_LEN/128, HEADS, BATCH);
        attn_mma_kernel<<<grid, 256, ATT_SMEM>>>(out);
    }
}

// round 16
// speedup vs baseline: 1.4294x; 1.2138x over previous
#include <cuda_runtime.h>
#include <cuda_bf16.h>
#include <cuda_fp16.h>
#include <cstdint>
#include <cstddef>

#define S_LEN 4096
#define BATCH 2
#define EMB   1024
#define HEADS 8
#define HD    128
#define WINW  256
#define SPAD  (S_LEN + 2*WINW)   // 4608

// Split-bf16 Q/K/V in attention layout (written by GEMM epilogue)
__device__ __align__(16) __nv_bfloat16 g_Qh[BATCH*HEADS*S_LEN*HD];
__device__ __align__(16) __nv_bfloat16 g_Ql[BATCH*HEADS*S_LEN*HD];
__device__ __align__(16) __nv_bfloat16 g_Kh[BATCH*HEADS*SPAD*HD];
__device__ __align__(16) __nv_bfloat16 g_Kl[BATCH*HEADS*SPAD*HD];
__device__ __align__(16) __nv_bfloat16 g_Vh[BATCH*HEADS*SPAD*HD];
__device__ __align__(16) __nv_bfloat16 g_Vl[BATCH*HEADS*SPAD*HD];

// GEMM inputs: X fp16 hi-only, W split fp16 hi/lo
__device__ __align__(16) __half g_Xh[8192*1024];
__device__ __align__(16) __half g_Wh[3*1024*1024];
__device__ __align__(16) __half g_Wl[3*1024*1024];

// ---------------------------------------------------------------------------
// helpers
// ---------------------------------------------------------------------------
__device__ __forceinline__ uint32_t smem_to_u32(const void* p) {
    uint32_t a;
    asm("{ .reg .u64 t; cvta.to.shared.u64 t, %1; cvt.u32.u64 %0, t; }"
        : "=r"(a) : "l"(p));
    return a;
}
__device__ __forceinline__ void cp_async16(uint32_t dst, const void* src) {
    asm volatile("cp.async.cg.shared.global [%0], [%1], 16;"
                 :: "r"(dst), "l"(src) : "memory");
}
#define CP_COMMIT() asm volatile("cp.async.commit_group;" ::: "memory")
#define CP_WAIT0()  asm volatile("cp.async.wait_group 0;" ::: "memory")
#define CP_WAIT1()  asm volatile("cp.async.wait_group 1;" ::: "memory")

__device__ __forceinline__ void ldmatrix_x4(uint32_t* r, uint32_t addr) {
    asm volatile("ldmatrix.sync.aligned.m8n8.x4.shared.b16 {%0,%1,%2,%3}, [%4];"
                 : "=r"(r[0]), "=r"(r[1]), "=r"(r[2]), "=r"(r[3]) : "r"(addr));
}
__device__ __forceinline__ void ldmatrix_x4_trans(uint32_t* r, uint32_t addr) {
    asm volatile("ldmatrix.sync.aligned.m8n8.x4.trans.shared.b16 {%0,%1,%2,%3}, [%4];"
                 : "=r"(r[0]), "=r"(r[1]), "=r"(r[2]), "=r"(r[3]) : "r"(addr));
}
// bf16 mma (attention)
__device__ __forceinline__ void mma16816(float* c, const uint32_t* a,
                                         const uint32_t* b) {
    asm volatile(
        "mma.sync.aligned.m16n8k16.row.col.f32.bf16.bf16.f32 "
        "{%0,%1,%2,%3}, {%4,%5,%6,%7}, {%8,%9}, {%0,%1,%2,%3};"
        : "+f"(c[0]), "+f"(c[1]), "+f"(c[2]), "+f"(c[3])
        : "r"(a[0]), "r"(a[1]), "r"(a[2]), "r"(a[3]), "r"(b[0]), "r"(b[1]));
}
// fp16 mma (GEMM)
__device__ __forceinline__ void mma16816h(float* c, const uint32_t* a,
                                          const uint32_t* b) {
    asm volatile(
        "mma.sync.aligned.m16n8k16.row.col.f32.f16.f16.f32 "
        "{%0,%1,%2,%3}, {%4,%5,%6,%7}, {%8,%9}, {%0,%1,%2,%3};"
        : "+f"(c[0]), "+f"(c[1]), "+f"(c[2]), "+f"(c[3])
        : "r"(a[0]), "r"(a[1]), "r"(a[2]), "r"(a[3]), "r"(b[0]), "r"(b[1]));
}
__device__ __forceinline__ uint32_t pack_bf16x2(float lo, float hi) {
    uint32_t r;
    asm("cvt.rn.bf16x2.f32 %0, %1, %2;" : "=r"(r) : "f"(hi), "f"(lo));
    return r;
}

// ---------------------------------------------------------------------------
// Converts: X -> fp16 hi (view-scramble gather); W -> fp16 hi/lo split
// ---------------------------------------------------------------------------
__global__ void convert_x_kernel(const float* __restrict__ val)
{
    int i = blockIdx.x * blockDim.x + threadIdx.x;
    if (i >= 8192*1024) return;
    int r = i >> 10, k = i & 1023;
    int b = r >> 12, s = r & 4095;
    g_Xh[i] = __float2half_rn(val[s*2048 + b*1024 + k]);
}

__global__ void convert_w_kernel(const float* __restrict__ Wq,
                                 const float* __restrict__ Wk,
                                 const float* __restrict__ Wv)
{
    int i = blockIdx.x * blockDim.x + threadIdx.x;
    if (i >= 3*1024*1024) return;
    int mat = i >> 20;
    const float* W = (mat == 0) ? Wq : (mat == 1 ? Wk : Wv);
    float f = W[i & 0xFFFFF];
    __half h = __float2half_rn(f);
    g_Wh[i] = h;
    g_Wl[i] = __float2half_rn(f - __half2float(h));
}

// ---------------------------------------------------------------------------
// Zero the pad rows of K/V (bf16 split arrays)
// ---------------------------------------------------------------------------
__global__ void zero_pads_kernel()
{
    int i = blockIdx.x * blockDim.x + threadIdx.x;
    const int total = BATCH*HEADS * (2*WINW) * HD;
    if (i >= total) return;
    int d  = i & (HD-1);
    int t  = i >> 7;
    int jr = t & (2*WINW - 1);
    int bh = t >> 9;
    int jpad = (jr < WINW) ? jr : (S_LEN + jr);
    size_t off = ((size_t)bh*SPAD + jpad)*HD + d;
    __nv_bfloat16 z = __float2bfloat16(0.0f);
    g_Kh[off] = z; g_Kl[off] = z;
    g_Vh[off] = z; g_Vl[off] = z;
}

// ---------------------------------------------------------------------------
// Warp-MMA GEMM v4: CTA 128x128, 4 warps, warp tile 64x64.
// fp16 2-product scheme: C = Xh*Wh + Xh*Wl (X hi-only).
// Per warp k-step: 12 LDSM vs 64 HMMA -> tensor-bound, HMMA count -33%.
// K-tile 32, cp.async double buffer. Stage = [Ah, Bh, Bl].
// ---------------------------------------------------------------------------
#define BK 32
#define NKT 32                    // 1024 / 32
#define LDSTR 40                  // smem row stride in fp16 (80 B)
#define VAR_BYTES (128*LDSTR*2)   // 10240
#define STAGE_BYTES (3*VAR_BYTES) // 30720: [Ah, Bh, Bl]
#define GEMM_SMEM (2*STAGE_BYTES) // 61440

__global__ __launch_bounds__(128) void qkv_mma_kernel(
    const float* __restrict__ bq, const float* __restrict__ bk,
    const float* __restrict__ bv)
{
    extern __shared__ char smem[];
    const uint32_t smem_base = smem_to_u32(smem);
    const int tid  = threadIdx.x;
    const int wid  = tid >> 5;
    const int lane = tid & 31;

    const int col0 = blockIdx.x * 128;
    const int row0 = blockIdx.y * 128;
    const int mat  = blockIdx.z;
    const float* bia = (mat == 0) ? bq : (mat == 1 ? bk : bv);

    const __half* Wh = g_Wh + (size_t)mat * 1048576;
    const __half* Wl = g_Wl + (size_t)mat * 1048576;

    const __half* srcs[3] = { g_Xh, Wh, Wl };
    const int vrow0[3] = { row0, col0, col0 };

    // warp layout 2x2; warp tile 64x64
    const int warp_m0 = (wid & 1) * 64;
    const int warp_n0 = (wid >> 1) * 64;

    const int offA_row = (lane & 7) + (lane & 8);
    const int offA_k   = (lane & 16) >> 1;
    const int offB_row = (lane & 7) + ((lane & 16) >> 1);
    const int offB_k   = lane & 8;

    float acc[4][8][4];
    #pragma unroll
    for (int mt = 0; mt < 4; mt++)
        #pragma unroll
        for (int nf = 0; nf < 8; nf++)
            acc[mt][nf][0] = acc[mt][nf][1] = acc[mt][nf][2] = acc[mt][nf][3] = 0.f;

    // prefetch tile 0: 1536 16B-chunks over 128 threads = 12 each
    {
        const uint32_t sb = smem_base;
        #pragma unroll
        for (int t = 0; t < 12; t++) {
            const int i = tid + t*128;
            const int v = i >> 9, idx = i & 511;
            const int row = idx >> 2, quad = idx & 3;
            cp_async16(sb + v*VAR_BYTES + (row*LDSTR + quad*8)*2,
                       srcs[v] + (size_t)(vrow0[v] + row)*1024 + quad*8);
        }
        CP_COMMIT();
    }

    for (int kt = 0; kt < NKT; kt++) {
        if (kt + 1 < NKT) {
            const uint32_t sb = smem_base + ((kt+1) & 1) * STAGE_BYTES;
            const int k0 = (kt+1) * BK;
            #pragma unroll
            for (int t = 0; t < 12; t++) {
                const int i = tid + t*128;
                const int v = i >> 9, idx = i & 511;
                const int row = idx >> 2, quad = idx & 3;
                cp_async16(sb + v*VAR_BYTES + (row*LDSTR + quad*8)*2,
                           srcs[v] + (size_t)(vrow0[v] + row)*1024 + k0 + quad*8);
            }
            CP_COMMIT();
            CP_WAIT1();
        } else {
            CP_WAIT0();
        }
        __syncthreads();

        const uint32_t sb = smem_base + (kt & 1) * STAGE_BYTES;
        const uint32_t aH = sb;
        const uint32_t bH = sb + VAR_BYTES, bL = sb + 2*VAR_BYTES;

        #pragma unroll
        for (int ks = 0; ks < 2; ks++) {
            const int kk = ks * 16;
            // load ALL fragments for this k-step first
            uint32_t ahf[4][4], bh4[4][4], bl4[4][4];
            #pragma unroll
            for (int mt = 0; mt < 4; mt++) {
                const uint32_t ro = (uint32_t)((warp_m0 + mt*16 + offA_row)*LDSTR
                                               + kk + offA_k) * 2;
                ldmatrix_x4(ahf[mt], aH + ro);
            }
            #pragma unroll
            for (int np = 0; np < 4; np++) {
                const uint32_t ro = (uint32_t)((warp_n0 + np*16 + offB_row)*LDSTR
                                               + kk + offB_k) * 2;
                ldmatrix_x4(bh4[np], bH + ro);
                ldmatrix_x4(bl4[np], bL + ro);
            }
            // product-major passes: consecutive MMAs hit distinct accumulators
            #pragma unroll
            for (int np = 0; np < 4; np++)
                #pragma unroll
                for (int mt = 0; mt < 4; mt++) {
                    mma16816h(acc[mt][2*np],   ahf[mt], &bh4[np][0]);
                    mma16816h(acc[mt][2*np+1], ahf[mt], &bh4[np][2]);
                }
            #pragma unroll
            for (int np = 0; np < 4; np++)
                #pragma unroll
                for (int mt = 0; mt < 4; mt++) {
                    mma16816h(acc[mt][2*np],   ahf[mt], &bl4[np][0]);
                    mma16816h(acc[mt][2*np+1], ahf[mt], &bl4[np][2]);
                }
        }
        __syncthreads();
    }

    // ---- epilogue: bias (+Q scale), split-bf16 write, view-scramble scatter ----
    const float scale = 0.08838834764831845f;   // 1/sqrt(128)
    #pragma unroll
    for (int mt = 0; mt < 4; mt++) {
        #pragma unroll
        for (int nf = 0; nf < 8; nf++) {
            const int col = col0 + warp_n0 + nf*8 + (lane & 3)*2;
            const int h   = col >> 7;
            const int dd  = col & 127;
            const float b0 = bia[col], b1 = bia[col+1];
            #pragma unroll
            for (int half_i = 0; half_i < 2; half_i++) {
                const int r  = row0 + warp_m0 + mt*16 + (lane >> 2) + half_i*8;
                const int bp = r & 1;
                const int sp = r >> 1;
                float v0 = acc[mt][nf][half_i*2+0] + b0;
                float v1 = acc[mt][nf][half_i*2+1] + b1;
                size_t idx;
                __nv_bfloat16* ah;
                __nv_bfloat16* al;
                if (mat == 0) {
                    v0 *= scale; v1 *= scale;
                    idx = ((size_t)(bp*HEADS + h)*S_LEN + sp)*HD + dd;
                    ah = g_Qh; al = g_Ql;
                } else {
                    idx = ((size_t)(bp*HEADS + h)*SPAD + (sp + WINW))*HD + dd;
                    ah = (mat == 1) ? g_Kh : g_Vh;
                    al = (mat == 1) ? g_Kl : g_Vl;
                }
                __nv_bfloat16 h0 = __float2bfloat16(v0);
                __nv_bfloat16 h1 = __float2bfloat16(v1);
                __nv_bfloat162 hv; hv.x = h0; hv.y = h1;
                __nv_bfloat162 lv;
                lv.x = __float2bfloat16(v0 - __bfloat162float(h0));
                lv.y = __float2bfloat16(v1 - __bfloat162float(h1));
                *(__nv_bfloat162*)(ah + idx) = hv;
                *(__nv_bfloat162*)(al + idx) = lv;
            }
        }
    }
}

// ---------------------------------------------------------------------------
// Banded flash attention via mma.sync (unchanged from 683.6us kernel):
//  - Q fragments register-cached; KV chunks double-buffered via cp.async
//  - per-warp chunk skip; split products issued at accumulator distance 4
// CTA = 128 queries of one (b',h); 8 warps x 16 queries; 10 chunks of 64 keys.
// ---------------------------------------------------------------------------
#define SSTR 136                       // smem row stride in bf16 (272 B)
#define QV_BYTES (128*SSTR*2)          // 34816 per Q var
#define KV_VAR   (64*SSTR*2)           // 17408 per KV var
#define KV_STAGE (4*KV_VAR)            // 69632: [Kh, Kl, Vh, Vl]
#define ATT_SMEM (2*QV_BYTES + 2*KV_STAGE)   // 208896

__global__ __launch_bounds__(256, 1) void attn_mma_kernel(float* __restrict__ out)
{
    extern __shared__ char smem[];
    const uint32_t sb = smem_to_u32(smem);
    const uint32_t sQh = sb, sQl = sb + QV_BYTES;
    const uint32_t sKV = sb + 2*QV_BYTES;     // two stages of [Kh,Kl,Vh,Vl]

    const int s0  = blockIdx.x * 128;
    const int h   = blockIdx.y;
    const int bp  = blockIdx.z;
    const int bh  = bp*HEADS + h;
    const int tid = threadIdx.x;
    const int wid = tid >> 5;
    const int lane = tid & 31;

    const __nv_bfloat16* Qhg = g_Qh + ((size_t)bh*S_LEN + s0)*HD;
    const __nv_bfloat16* Qlg = g_Ql + ((size_t)bh*S_LEN + s0)*HD;
    const size_t kvbase = ((size_t)bh*SPAD + s0)*HD;
    const __nv_bfloat16* gKV[4] = {
        g_Kh + kvbase, g_Kl + kvbase, g_Vh + kvbase, g_Vl + kvbase };

    // stage Q via cp.async (group 0)
    #pragma unroll
    for (int t = 0; t < 16; t++) {
        const int i = tid + t*256;          // 0..4095
        const int v = i >> 11, idx = i & 2047;
        const int row = idx >> 4, ch = idx & 15;
        cp_async16((v ? sQl : sQh) + row*272 + ch*16,
                   (v ? Qlg : Qhg) + (size_t)row*HD + ch*8);
    }
    CP_COMMIT();

    // prefetch KV chunk 0 into stage 0 (group 1)
    #pragma unroll
    for (int t = 0; t < 16; t++) {
        const int i = tid + t*256;
        const int v = i >> 10, idx = i & 1023;
        const int row = idx >> 4, ch = idx & 15;
        cp_async16(sKV + v*KV_VAR + row*272 + ch*16,
                   gKV[v] + (size_t)row*HD + ch*8);
    }
    CP_COMMIT();

    const int warp_q0 = wid * 16;
    const int offA_row = (lane & 7) + (lane & 8);
    const int offA_k   = (lane & 16) >> 1;
    const int offB_row = (lane & 7) + ((lane & 16) >> 1);
    const int offB_k   = lane & 8;
    const int vt_r = lane & 7;
    const int vt_j = ((lane >> 3) & 1) * 8;
    const int vt_d = ((lane >> 4) & 1) * 8;

    const int qlo = warp_q0 + (lane >> 2);
    const int qhi = qlo + 8;

    CP_WAIT1();            // Q ready (chunk 0 may still be in flight)
    __syncthreads();

    // cache Q fragments in registers for all 8 k-steps
    uint32_t qh[8][4], ql[8][4];
    #pragma unroll
    for (int ks = 0; ks < 8; ks++) {
        const uint32_t qo = (uint32_t)((warp_q0 + offA_row)*SSTR
                                       + ks*16 + offA_k) * 2;
        ldmatrix_x4(qh[ks], sQh + qo);
        ldmatrix_x4(ql[ks], sQl + qo);
    }

    float of[16][4];
    #pragma unroll
    for (int f = 0; f < 16; f++)
        of[f][0] = of[f][1] = of[f][2] = of[f][3] = 0.f;
    float m_lo = -1e30f, m_hi = -1e30f, l_lo = 0.f, l_hi = 0.f;

    for (int c = 0; c < 10; c++) {
        // prefetch chunk c+1 into the other stage
        if (c < 9) {
            const uint32_t dstS = sKV + ((c+1) & 1) * KV_STAGE;
            const size_t srcOff = (size_t)(c+1)*64*HD;
            #pragma unroll
            for (int t = 0; t < 16; t++) {
                const int i = tid + t*256;
                const int v = i >> 10, idx = i & 1023;
                const int row = idx >> 4, ch = idx & 15;
                cp_async16(dstS + v*KV_VAR + row*272 + ch*16,
                           gKV[v] + srcOff + (size_t)row*HD + ch*8);
            }
            CP_COMMIT();
            CP_WAIT1();        // chunk c complete
        } else {
            CP_WAIT0();
        }
        __syncthreads();

        // per-warp band test (uniform across the warp)
        const bool active = (c*64 + 63 >= warp_q0) && (c*64 <= warp_q0 + 527);
        if (active) {
            const uint32_t stg = sKV + (c & 1) * KV_STAGE;
            const uint32_t cKh = stg, cKl = stg + KV_VAR;
            const uint32_t cVh = stg + 2*KV_VAR, cVl = stg + 3*KV_VAR;

            // ---- S = Q K^T (64 keys), split-bf16, fp32 accum ----
            float sf[8][4];
            #pragma unroll
            for (int f = 0; f < 8; f++)
                sf[f][0] = sf[f][1] = sf[f][2] = sf[f][3] = 0.f;

            #pragma unroll
            for (int ks = 0; ks < 8; ks++) {
                #pragma unroll
                for (int ng2 = 0; ng2 < 2; ng2++) {
                    uint32_t kh4[2][4], kl4[2][4];
                    #pragma unroll
                    for (int s = 0; s < 2; s++) {
                        const int ng = 2*ng2 + s;
                        const uint32_t ko = (uint32_t)((ng*16 + offB_row)*SSTR
                                                       + ks*16 + offB_k) * 2;
                        ldmatrix_x4(kh4[s], cKh + ko);
                        ldmatrix_x4(kl4[s], cKl + ko);
                    }
                    #pragma unroll
                    for (int s = 0; s < 2; s++) {
                        const int ng = 2*ng2 + s;
                        mma16816(sf[2*ng],   qh[ks], &kh4[s][0]);
                        mma16816(sf[2*ng+1], qh[ks], &kh4[s][2]);
                    }
                    #pragma unroll
                    for (int s = 0; s < 2; s++) {
                        const int ng = 2*ng2 + s;
                        mma16816(sf[2*ng],   qh[ks], &kl4[s][0]);
                        mma16816(sf[2*ng+1], qh[ks], &kl4[s][2]);
                    }
                    #pragma unroll
                    for (int s = 0; s < 2; s++) {
                        const int ng = 2*ng2 + s;
                        mma16816(sf[2*ng],   ql[ks], &kh4[s][0]);
                        mma16816(sf[2*ng+1], ql[ks], &kh4[s][2]);
                    }
                }
            }

            // ---- masked online softmax ----
            const int kb = c*64 + (lane & 3)*2;
            float mxlo = -1e30f, mxhi = -1e30f;
            #pragma unroll
            for (int f = 0; f < 8; f++) {
                #pragma unroll
                for (int j = 0; j < 2; j++) {
                    const int kc = kb + f*8 + j;
                    const bool vlo = (kc >= qlo) && (kc <= qlo + 512);
                    const bool vhi = (kc >= qhi) && (kc <= qhi + 512);
                    const float slo = vlo ? sf[f][j]   : -1e30f;
                    const float shi = vhi ? sf[f][2+j] : -1e30f;
                    sf[f][j]   = slo;  mxlo = fmaxf(mxlo, slo);
                    sf[f][2+j] = shi;  mxhi = fmaxf(mxhi, shi);
                }
            }
            mxlo = fmaxf(mxlo, __shfl_xor_sync(0xffffffffu, mxlo, 1));
            mxlo = fmaxf(mxlo, __shfl_xor_sync(0xffffffffu, mxlo, 2));
            mxhi = fmaxf(mxhi, __shfl_xor_sync(0xffffffffu, mxhi, 1));
            mxhi = fmaxf(mxhi, __shfl_xor_sync(0xffffffffu, mxhi, 2));

            const float mnlo = fmaxf(m_lo, mxlo);
            const float mnhi = fmaxf(m_hi, mxhi);
            const float alo = __expf(m_lo - mnlo);
            const float ahi = __expf(m_hi - mnhi);
            m_lo = mnlo; m_hi = mnhi;

            float sumlo = 0.f, sumhi = 0.f;
            #pragma unroll
            for (int f = 0; f < 8; f++) {
                #pragma unroll
                for (int j = 0; j < 2; j++) {
                    const int kc = kb + f*8 + j;
                    const bool vlo = (kc >= qlo) && (kc <= qlo + 512);
                    const bool vhi = (kc >= qhi) && (kc <= qhi + 512);
                    const float plo = vlo ? __expf(sf[f][j]   - mnlo) : 0.f;
                    const float phi = vhi ? __expf(sf[f][2+j] - mnhi) : 0.f;
                    sf[f][j] = plo;   sumlo += plo;
                    sf[f][2+j] = phi; sumhi += phi;
                }
            }
            sumlo += __shfl_xor_sync(0xffffffffu, sumlo, 1);
            sumlo += __shfl_xor_sync(0xffffffffu, sumlo, 2);
            sumhi += __shfl_xor_sync(0xffffffffu, sumhi, 1);
            sumhi += __shfl_xor_sync(0xffffffffu, sumhi, 2);
            l_lo = l_lo*alo + sumlo;
            l_hi = l_hi*ahi + sumhi;

            #pragma unroll
            for (int f = 0; f < 16; f++) {
                of[f][0] *= alo; of[f][1] *= alo;
                of[f][2] *= ahi; of[f][3] *= ahi;
            }

            // ---- O += P V, split-bf16, distance-4 accumulator reuse ----
            #pragma unroll
            for (int t = 0; t < 4; t++) {
                uint32_t ah[4], al[4];
                #pragma unroll
                for (int g = 0; g < 4; g++) {
                    const int fr = 2*t + (g >> 1);
                    const int b0 = (g & 1) * 2;
                    const float p0 = sf[fr][b0], p1 = sf[fr][b0+1];
                    const float h0 = __bfloat162float(__float2bfloat16(p0));
                    const float h1 = __bfloat162float(__float2bfloat16(p1));
                    ah[g] = pack_bf16x2(h0, h1);
                    al[g] = pack_bf16x2(p0 - h0, p1 - h1);
                }
                #pragma unroll
                for (int dg2 = 0; dg2 < 4; dg2++) {
                    uint32_t vh4[2][4], vl4[2][4];
                    #pragma unroll
                    for (int s = 0; s < 2; s++) {
                        const int dg = 2*dg2 + s;
                        const uint32_t vo = (uint32_t)((t*16 + vt_j + vt_r)*SSTR
                                                       + dg*16 + vt_d) * 2;
                        ldmatrix_x4_trans(vh4[s], cVh + vo);
                        ldmatrix_x4_trans(vl4[s], cVl + vo);
                    }
                    #pragma unroll
                    for (int s = 0; s < 2; s++) {
                        const int dg = 2*dg2 + s;
                        mma16816(of[2*dg],   ah, &vh4[s][0]);
                        mma16816(of[2*dg+1], ah, &vh4[s][2]);
                    }
                    #pragma unroll
                    for (int s = 0; s < 2; s++) {
                        const int dg = 2*dg2 + s;
                        mma16816(of[2*dg],   ah, &vl4[s][0]);
                        mma16816(of[2*dg+1], ah, &vl4[s][2]);
                    }
                    #pragma unroll
                    for (int s = 0; s < 2; s++) {
                        const int dg = 2*dg2 + s;
                        mma16816(of[2*dg],   al, &vh4[s][0]);
                        mma16816(of[2*dg+1], al, &vh4[s][2]);
                    }
                }
            }
        }
        __syncthreads();
    }

    // ---- write out: out[s'][b'][h*128+d] ----
    const float invlo = 1.f / l_lo;
    const float invhi = 1.f / l_hi;
    const int sqlo = s0 + qlo;
    const int sqhi = s0 + qhi;
    const size_t obase = (size_t)bp*1024 + h*128 + (lane & 3)*2;
    #pragma unroll
    for (int f = 0; f < 16; f++) {
        const int d = f*8;
        float2 o1; o1.x = of[f][0]*invlo; o1.y = of[f][1]*invlo;
        *(float2*)&out[(size_t)sqlo*2048 + obase + d] = o1;
        float2 o2; o2.x = of[f][2]*invhi; o2.y = of[f][3]*invhi;
        *(float2*)&out[(size_t)sqhi*2048 + obase + d] = o2;
    }
}

// ---------------------------------------------------------------------------
extern "C" void kernel_launch(void* const* d_in, const int* in_sizes, int n_in,
                              void* d_out, int out_size)
{
    (void)in_sizes; (void)n_in; (void)out_size;
    const float* val = (const float*)d_in[0];
    const float* Wq  = (const float*)d_in[1];
    const float* bq  = (const float*)d_in[2];
    const float* Wk  = (const float*)d_in[3];
    const float* bk  = (const float*)d_in[4];
    const float* Wv  = (const float*)d_in[5];
    const float* bv  = (const float*)d_in[6];
    float* out = (float*)d_out;

    cudaFuncSetAttribute(qkv_mma_kernel, cudaFuncAttributeMaxDynamicSharedMemorySize,
                         GEMM_SMEM);
    cudaFuncSetAttribute(attn_mma_kernel, cudaFuncAttributeMaxDynamicSharedMemorySize,
                         ATT_SMEM);

    convert_x_kernel<<<(8192*1024)/256, 256>>>(val);
    convert_w_kernel<<<(3*1024*1024)/256, 256>>>(Wq, Wk, Wv);
    {
        const int total = BATCH*HEADS * (2*WINW) * HD;
        zero_pads_kernel<<<(total + 255)/256, 256>>>();
    }
    {
        dim3 grid(1024/128, 8192/128, 3);
        qkv_mma_kernel<<<grid, 128, GEMM_SMEM>>>(bq, bk, bv);
    }
    {
        dim3 grid(S_LEN/128, HEADS, BATCH);
        attn_mma_kernel<<<grid, 256, ATT_SMEM>>>(out);
    }
}

// round 17
// speedup vs baseline: 1.9266x; 1.3478x over previous
#include <cuda_runtime.h>
#include <cuda_bf16.h>
#include <cuda_fp16.h>
#include <cstdint>
#include <cstddef>

#define S_LEN 4096
#define BATCH 2
#define EMB   1024
#define HEADS 8
#define HD    128
#define WINW  256
#define SPAD  (S_LEN + 2*WINW)   // 4608

// Split-bf16 Q/K/V in attention layout (written by GEMM epilogue)
__device__ __align__(16) __nv_bfloat16 g_Qh[BATCH*HEADS*S_LEN*HD];
__device__ __align__(16) __nv_bfloat16 g_Ql[BATCH*HEADS*S_LEN*HD];
__device__ __align__(16) __nv_bfloat16 g_Kh[BATCH*HEADS*SPAD*HD];
__device__ __align__(16) __nv_bfloat16 g_Kl[BATCH*HEADS*SPAD*HD];
__device__ __align__(16) __nv_bfloat16 g_Vh[BATCH*HEADS*SPAD*HD];
__device__ __align__(16) __nv_bfloat16 g_Vl[BATCH*HEADS*SPAD*HD];

// GEMM inputs: X and W, fp16 (single product)
__device__ __align__(16) __half g_Xh[8192*1024];
__device__ __align__(16) __half g_Wh[3*1024*1024];

// ---------------------------------------------------------------------------
// helpers
// ---------------------------------------------------------------------------
__device__ __forceinline__ uint32_t smem_to_u32(const void* p) {
    uint32_t a;
    asm("{ .reg .u64 t; cvta.to.shared.u64 t, %1; cvt.u32.u64 %0, t; }"
        : "=r"(a) : "l"(p));
    return a;
}
__device__ __forceinline__ void cp_async16(uint32_t dst, const void* src) {
    asm volatile("cp.async.cg.shared.global [%0], [%1], 16;"
                 :: "r"(dst), "l"(src) : "memory");
}
#define CP_COMMIT() asm volatile("cp.async.commit_group;" ::: "memory")
#define CP_WAIT0()  asm volatile("cp.async.wait_group 0;" ::: "memory")
#define CP_WAIT1()  asm volatile("cp.async.wait_group 1;" ::: "memory")

__device__ __forceinline__ void ldmatrix_x4(uint32_t* r, uint32_t addr) {
    asm volatile("ldmatrix.sync.aligned.m8n8.x4.shared.b16 {%0,%1,%2,%3}, [%4];"
                 : "=r"(r[0]), "=r"(r[1]), "=r"(r[2]), "=r"(r[3]) : "r"(addr));
}
__device__ __forceinline__ void ldmatrix_x4_trans(uint32_t* r, uint32_t addr) {
    asm volatile("ldmatrix.sync.aligned.m8n8.x4.trans.shared.b16 {%0,%1,%2,%3}, [%4];"
                 : "=r"(r[0]), "=r"(r[1]), "=r"(r[2]), "=r"(r[3]) : "r"(addr));
}
// bf16 mma (attention)
__device__ __forceinline__ void mma16816(float* c, const uint32_t* a,
                                         const uint32_t* b) {
    asm volatile(
        "mma.sync.aligned.m16n8k16.row.col.f32.bf16.bf16.f32 "
        "{%0,%1,%2,%3}, {%4,%5,%6,%7}, {%8,%9}, {%0,%1,%2,%3};"
        : "+f"(c[0]), "+f"(c[1]), "+f"(c[2]), "+f"(c[3])
        : "r"(a[0]), "r"(a[1]), "r"(a[2]), "r"(a[3]), "r"(b[0]), "r"(b[1]));
}
// fp16 mma (GEMM)
__device__ __forceinline__ void mma16816h(float* c, const uint32_t* a,
                                          const uint32_t* b) {
    asm volatile(
        "mma.sync.aligned.m16n8k16.row.col.f32.f16.f16.f32 "
        "{%0,%1,%2,%3}, {%4,%5,%6,%7}, {%8,%9}, {%0,%1,%2,%3};"
        : "+f"(c[0]), "+f"(c[1]), "+f"(c[2]), "+f"(c[3])
        : "r"(a[0]), "r"(a[1]), "r"(a[2]), "r"(a[3]), "r"(b[0]), "r"(b[1]));
}
__device__ __forceinline__ uint32_t pack_bf16x2(float lo, float hi) {
    uint32_t r;
    asm("cvt.rn.bf16x2.f32 %0, %1, %2;" : "=r"(r) : "f"(hi), "f"(lo));
    return r;
}

// ---------------------------------------------------------------------------
// Converts: X -> fp16 (view-scramble gather); W -> fp16
// ---------------------------------------------------------------------------
__global__ void convert_x_kernel(const float* __restrict__ val)
{
    int i = blockIdx.x * blockDim.x + threadIdx.x;
    if (i >= 8192*1024) return;
    int r = i >> 10, k = i & 1023;
    int b = r >> 12, s = r & 4095;
    g_Xh[i] = __float2half_rn(val[s*2048 + b*1024 + k]);
}

__global__ void convert_w_kernel(const float* __restrict__ Wq,
                                 const float* __restrict__ Wk,
                                 const float* __restrict__ Wv)
{
    int i = blockIdx.x * blockDim.x + threadIdx.x;
    if (i >= 3*1024*1024) return;
    int mat = i >> 20;
    const float* W = (mat == 0) ? Wq : (mat == 1 ? Wk : Wv);
    g_Wh[i] = __float2half_rn(W[i & 0xFFFFF]);
}

// ---------------------------------------------------------------------------
// Zero the pad rows of K/V (bf16 split arrays)
// ---------------------------------------------------------------------------
__global__ void zero_pads_kernel()
{
    int i = blockIdx.x * blockDim.x + threadIdx.x;
    const int total = BATCH*HEADS * (2*WINW) * HD;
    if (i >= total) return;
    int d  = i & (HD-1);
    int t  = i >> 7;
    int jr = t & (2*WINW - 1);
    int bh = t >> 9;
    int jpad = (jr < WINW) ? jr : (S_LEN + jr);
    size_t off = ((size_t)bh*SPAD + jpad)*HD + d;
    __nv_bfloat16 z = __float2bfloat16(0.0f);
    g_Kh[off] = z; g_Kl[off] = z;
    g_Vh[off] = z; g_Vl[off] = z;
}

// ---------------------------------------------------------------------------
// Warp-MMA GEMM v5: CTA 128x128, 4 warps, warp tile 64x64.
// Pure fp16 single product: C = Xh*Wh.
// Per warp k-step: 8 LDSM vs 32 HMMA -> tensor-bound, HMMA count halved again.
// K-tile 32, cp.async double buffer. Stage = [Ah, Bh].
// ---------------------------------------------------------------------------
#define BK 32
#define NKT 32                    // 1024 / 32
#define LDSTR 40                  // smem row stride in fp16 (80 B)
#define VAR_BYTES (128*LDSTR*2)   // 10240
#define STAGE_BYTES (2*VAR_BYTES) // 20480: [Ah, Bh]
#define GEMM_SMEM (2*STAGE_BYTES) // 40960

__global__ __launch_bounds__(128) void qkv_mma_kernel(
    const float* __restrict__ bq, const float* __restrict__ bk,
    const float* __restrict__ bv)
{
    extern __shared__ char smem[];
    const uint32_t smem_base = smem_to_u32(smem);
    const int tid  = threadIdx.x;
    const int wid  = tid >> 5;
    const int lane = tid & 31;

    const int col0 = blockIdx.x * 128;
    const int row0 = blockIdx.y * 128;
    const int mat  = blockIdx.z;
    const float* bia = (mat == 0) ? bq : (mat == 1 ? bk : bv);

    const __half* Wh = g_Wh + (size_t)mat * 1048576;

    const __half* srcs[2] = { g_Xh, Wh };
    const int vrow0[2] = { row0, col0 };

    // warp layout 2x2; warp tile 64x64
    const int warp_m0 = (wid & 1) * 64;
    const int warp_n0 = (wid >> 1) * 64;

    const int offA_row = (lane & 7) + (lane & 8);
    const int offA_k   = (lane & 16) >> 1;
    const int offB_row = (lane & 7) + ((lane & 16) >> 1);
    const int offB_k   = lane & 8;

    float acc[4][8][4];
    #pragma unroll
    for (int mt = 0; mt < 4; mt++)
        #pragma unroll
        for (int nf = 0; nf < 8; nf++)
            acc[mt][nf][0] = acc[mt][nf][1] = acc[mt][nf][2] = acc[mt][nf][3] = 0.f;

    // prefetch tile 0: 1024 16B-chunks over 128 threads = 8 each
    {
        const uint32_t sb = smem_base;
        #pragma unroll
        for (int t = 0; t < 8; t++) {
            const int i = tid + t*128;
            const int v = i >> 9, idx = i & 511;
            const int row = idx >> 2, quad = idx & 3;
            cp_async16(sb + v*VAR_BYTES + (row*LDSTR + quad*8)*2,
                       srcs[v] + (size_t)(vrow0[v] + row)*1024 + quad*8);
        }
        CP_COMMIT();
    }

    for (int kt = 0; kt < NKT; kt++) {
        if (kt + 1 < NKT) {
            const uint32_t sb = smem_base + ((kt+1) & 1) * STAGE_BYTES;
            const int k0 = (kt+1) * BK;
            #pragma unroll
            for (int t = 0; t < 8; t++) {
                const int i = tid + t*128;
                const int v = i >> 9, idx = i & 511;
                const int row = idx >> 2, quad = idx & 3;
                cp_async16(sb + v*VAR_BYTES + (row*LDSTR + quad*8)*2,
                           srcs[v] + (size_t)(vrow0[v] + row)*1024 + k0 + quad*8);
            }
            CP_COMMIT();
            CP_WAIT1();
        } else {
            CP_WAIT0();
        }
        __syncthreads();

        const uint32_t sb = smem_base + (kt & 1) * STAGE_BYTES;
        const uint32_t aH = sb;
        const uint32_t bH = sb + VAR_BYTES;

        #pragma unroll
        for (int ks = 0; ks < 2; ks++) {
            const int kk = ks * 16;
            uint32_t ahf[4][4], bh4[4][4];
            #pragma unroll
            for (int mt = 0; mt < 4; mt++) {
                const uint32_t ro = (uint32_t)((warp_m0 + mt*16 + offA_row)*LDSTR
                                               + kk + offA_k) * 2;
                ldmatrix_x4(ahf[mt], aH + ro);
            }
            #pragma unroll
            for (int np = 0; np < 4; np++) {
                const uint32_t ro = (uint32_t)((warp_n0 + np*16 + offB_row)*LDSTR
                                               + kk + offB_k) * 2;
                ldmatrix_x4(bh4[np], bH + ro);
            }
            #pragma unroll
            for (int np = 0; np < 4; np++)
                #pragma unroll
                for (int mt = 0; mt < 4; mt++) {
                    mma16816h(acc[mt][2*np],   ahf[mt], &bh4[np][0]);
                    mma16816h(acc[mt][2*np+1], ahf[mt], &bh4[np][2]);
                }
        }
        __syncthreads();
    }

    // ---- epilogue: bias (+Q scale), split-bf16 write, view-scramble scatter ----
    const float scale = 0.08838834764831845f;   // 1/sqrt(128)
    #pragma unroll
    for (int mt = 0; mt < 4; mt++) {
        #pragma unroll
        for (int nf = 0; nf < 8; nf++) {
            const int col = col0 + warp_n0 + nf*8 + (lane & 3)*2;
            const int h   = col >> 7;
            const int dd  = col & 127;
            const float b0 = bia[col], b1 = bia[col+1];
            #pragma unroll
            for (int half_i = 0; half_i < 2; half_i++) {
                const int r  = row0 + warp_m0 + mt*16 + (lane >> 2) + half_i*8;
                const int bp = r & 1;
                const int sp = r >> 1;
                float v0 = acc[mt][nf][half_i*2+0] + b0;
                float v1 = acc[mt][nf][half_i*2+1] + b1;
                size_t idx;
                __nv_bfloat16* ah;
                __nv_bfloat16* al;
                if (mat == 0) {
                    v0 *= scale; v1 *= scale;
                    idx = ((size_t)(bp*HEADS + h)*S_LEN + sp)*HD + dd;
                    ah = g_Qh; al = g_Ql;
                } else {
                    idx = ((size_t)(bp*HEADS + h)*SPAD + (sp + WINW))*HD + dd;
                    ah = (mat == 1) ? g_Kh : g_Vh;
                    al = (mat == 1) ? g_Kl : g_Vl;
                }
                __nv_bfloat16 h0 = __float2bfloat16(v0);
                __nv_bfloat16 h1 = __float2bfloat16(v1);
                __nv_bfloat162 hv; hv.x = h0; hv.y = h1;
                __nv_bfloat162 lv;
                lv.x = __float2bfloat16(v0 - __bfloat162float(h0));
                lv.y = __float2bfloat16(v1 - __bfloat162float(h1));
                *(__nv_bfloat162*)(ah + idx) = hv;
                *(__nv_bfloat162*)(al + idx) = lv;
            }
        }
    }
}

// ---------------------------------------------------------------------------
// Banded flash attention via mma.sync (unchanged from 563.2us kernel):
//  - Q fragments register-cached; KV chunks double-buffered via cp.async
//  - per-warp chunk skip; split products issued at accumulator distance 4
// CTA = 128 queries of one (b',h); 8 warps x 16 queries; 10 chunks of 64 keys.
// ---------------------------------------------------------------------------
#define SSTR 136                       // smem row stride in bf16 (272 B)
#define QV_BYTES (128*SSTR*2)          // 34816 per Q var
#define KV_VAR   (64*SSTR*2)           // 17408 per KV var
#define KV_STAGE (4*KV_VAR)            // 69632: [Kh, Kl, Vh, Vl]
#define ATT_SMEM (2*QV_BYTES + 2*KV_STAGE)   // 208896

__global__ __launch_bounds__(256, 1) void attn_mma_kernel(float* __restrict__ out)
{
    extern __shared__ char smem[];
    const uint32_t sb = smem_to_u32(smem);
    const uint32_t sQh = sb, sQl = sb + QV_BYTES;
    const uint32_t sKV = sb + 2*QV_BYTES;     // two stages of [Kh,Kl,Vh,Vl]

    const int s0  = blockIdx.x * 128;
    const int h   = blockIdx.y;
    const int bp  = blockIdx.z;
    const int bh  = bp*HEADS + h;
    const int tid = threadIdx.x;
    const int wid = tid >> 5;
    const int lane = tid & 31;

    const __nv_bfloat16* Qhg = g_Qh + ((size_t)bh*S_LEN + s0)*HD;
    const __nv_bfloat16* Qlg = g_Ql + ((size_t)bh*S_LEN + s0)*HD;
    const size_t kvbase = ((size_t)bh*SPAD + s0)*HD;
    const __nv_bfloat16* gKV[4] = {
        g_Kh + kvbase, g_Kl + kvbase, g_Vh + kvbase, g_Vl + kvbase };

    // stage Q via cp.async (group 0)
    #pragma unroll
    for (int t = 0; t < 16; t++) {
        const int i = tid + t*256;          // 0..4095
        const int v = i >> 11, idx = i & 2047;
        const int row = idx >> 4, ch = idx & 15;
        cp_async16((v ? sQl : sQh) + row*272 + ch*16,
                   (v ? Qlg : Qhg) + (size_t)row*HD + ch*8);
    }
    CP_COMMIT();

    // prefetch KV chunk 0 into stage 0 (group 1)
    #pragma unroll
    for (int t = 0; t < 16; t++) {
        const int i = tid + t*256;
        const int v = i >> 10, idx = i & 1023;
        const int row = idx >> 4, ch = idx & 15;
        cp_async16(sKV + v*KV_VAR + row*272 + ch*16,
                   gKV[v] + (size_t)row*HD + ch*8);
    }
    CP_COMMIT();

    const int warp_q0 = wid * 16;
    const int offA_row = (lane & 7) + (lane & 8);
    const int offA_k   = (lane & 16) >> 1;
    const int offB_row = (lane & 7) + ((lane & 16) >> 1);
    const int offB_k   = lane & 8;
    const int vt_r = lane & 7;
    const int vt_j = ((lane >> 3) & 1) * 8;
    const int vt_d = ((lane >> 4) & 1) * 8;

    const int qlo = warp_q0 + (lane >> 2);
    const int qhi = qlo + 8;

    CP_WAIT1();            // Q ready (chunk 0 may still be in flight)
    __syncthreads();

    // cache Q fragments in registers for all 8 k-steps
    uint32_t qh[8][4], ql[8][4];
    #pragma unroll
    for (int ks = 0; ks < 8; ks++) {
        const uint32_t qo = (uint32_t)((warp_q0 + offA_row)*SSTR
                                       + ks*16 + offA_k) * 2;
        ldmatrix_x4(qh[ks], sQh + qo);
        ldmatrix_x4(ql[ks], sQl + qo);
    }

    float of[16][4];
    #pragma unroll
    for (int f = 0; f < 16; f++)
        of[f][0] = of[f][1] = of[f][2] = of[f][3] = 0.f;
    float m_lo = -1e30f, m_hi = -1e30f, l_lo = 0.f, l_hi = 0.f;

    for (int c = 0; c < 10; c++) {
        // prefetch chunk c+1 into the other stage
        if (c < 9) {
            const uint32_t dstS = sKV + ((c+1) & 1) * KV_STAGE;
            const size_t srcOff = (size_t)(c+1)*64*HD;
            #pragma unroll
            for (int t = 0; t < 16; t++) {
                const int i = tid + t*256;
                const int v = i >> 10, idx = i & 1023;
                const int row = idx >> 4, ch = idx & 15;
                cp_async16(dstS + v*KV_VAR + row*272 + ch*16,
                           gKV[v] + srcOff + (size_t)row*HD + ch*8);
            }
            CP_COMMIT();
            CP_WAIT1();        // chunk c complete
        } else {
            CP_WAIT0();
        }
        __syncthreads();

        // per-warp band test (uniform across the warp)
        const bool active = (c*64 + 63 >= warp_q0) && (c*64 <= warp_q0 + 527);
        if (active) {
            const uint32_t stg = sKV + (c & 1) * KV_STAGE;
            const uint32_t cKh = stg, cKl = stg + KV_VAR;
            const uint32_t cVh = stg + 2*KV_VAR, cVl = stg + 3*KV_VAR;

            // ---- S = Q K^T (64 keys), split-bf16, fp32 accum ----
            float sf[8][4];
            #pragma unroll
            for (int f = 0; f < 8; f++)
                sf[f][0] = sf[f][1] = sf[f][2] = sf[f][3] = 0.f;

            #pragma unroll
            for (int ks = 0; ks < 8; ks++) {
                #pragma unroll
                for (int ng2 = 0; ng2 < 2; ng2++) {
                    uint32_t kh4[2][4], kl4[2][4];
                    #pragma unroll
                    for (int s = 0; s < 2; s++) {
                        const int ng = 2*ng2 + s;
                        const uint32_t ko = (uint32_t)((ng*16 + offB_row)*SSTR
                                                       + ks*16 + offB_k) * 2;
                        ldmatrix_x4(kh4[s], cKh + ko);
                        ldmatrix_x4(kl4[s], cKl + ko);
                    }
                    #pragma unroll
                    for (int s = 0; s < 2; s++) {
                        const int ng = 2*ng2 + s;
                        mma16816(sf[2*ng],   qh[ks], &kh4[s][0]);
                        mma16816(sf[2*ng+1], qh[ks], &kh4[s][2]);
                    }
                    #pragma unroll
                    for (int s = 0; s < 2; s++) {
                        const int ng = 2*ng2 + s;
                        mma16816(sf[2*ng],   qh[ks], &kl4[s][0]);
                        mma16816(sf[2*ng+1], qh[ks], &kl4[s][2]);
                    }
                    #pragma unroll
                    for (int s = 0; s < 2; s++) {
                        const int ng = 2*ng2 + s;
                        mma16816(sf[2*ng],   ql[ks], &kh4[s][0]);
                        mma16816(sf[2*ng+1], ql[ks], &kh4[s][2]);
                    }
                }
            }

            // ---- masked online softmax ----
            const int kb = c*64 + (lane & 3)*2;
            float mxlo = -1e30f, mxhi = -1e30f;
            #pragma unroll
            for (int f = 0; f < 8; f++) {
                #pragma unroll
                for (int j = 0; j < 2; j++) {
                    const int kc = kb + f*8 + j;
                    const bool vlo = (kc >= qlo) && (kc <= qlo + 512);
                    const bool vhi = (kc >= qhi) && (kc <= qhi + 512);
                    const float slo = vlo ? sf[f][j]   : -1e30f;
                    const float shi = vhi ? sf[f][2+j] : -1e30f;
                    sf[f][j]   = slo;  mxlo = fmaxf(mxlo, slo);
                    sf[f][2+j] = shi;  mxhi = fmaxf(mxhi, shi);
                }
            }
            mxlo = fmaxf(mxlo, __shfl_xor_sync(0xffffffffu, mxlo, 1));
            mxlo = fmaxf(mxlo, __shfl_xor_sync(0xffffffffu, mxlo, 2));
            mxhi = fmaxf(mxhi, __shfl_xor_sync(0xffffffffu, mxhi, 1));
            mxhi = fmaxf(mxhi, __shfl_xor_sync(0xffffffffu, mxhi, 2));

            const float mnlo = fmaxf(m_lo, mxlo);
            const float mnhi = fmaxf(m_hi, mxhi);
            const float alo = __expf(m_lo - mnlo);
            const float ahi = __expf(m_hi - mnhi);
            m_lo = mnlo; m_hi = mnhi;

            float sumlo = 0.f, sumhi = 0.f;
            #pragma unroll
            for (int f = 0; f < 8; f++) {
                #pragma unroll
                for (int j = 0; j < 2; j++) {
                    const int kc = kb + f*8 + j;
                    const bool vlo = (kc >= qlo) && (kc <= qlo + 512);
                    const bool vhi = (kc >= qhi) && (kc <= qhi + 512);
                    const float plo = vlo ? __expf(sf[f][j]   - mnlo) : 0.f;
                    const float phi = vhi ? __expf(sf[f][2+j] - mnhi) : 0.f;
                    sf[f][j] = plo;   sumlo += plo;
                    sf[f][2+j] = phi; sumhi += phi;
                }
            }
            sumlo += __shfl_xor_sync(0xffffffffu, sumlo, 1);
            sumlo += __shfl_xor_sync(0xffffffffu, sumlo, 2);
            sumhi += __shfl_xor_sync(0xffffffffu, sumhi, 1);
            sumhi += __shfl_xor_sync(0xffffffffu, sumhi, 2);
            l_lo = l_lo*alo + sumlo;
            l_hi = l_hi*ahi + sumhi;

            #pragma unroll
            for (int f = 0; f < 16; f++) {
                of[f][0] *= alo; of[f][1] *= alo;
                of[f][2] *= ahi; of[f][3] *= ahi;
            }

            // ---- O += P V, split-bf16, distance-4 accumulator reuse ----
            #pragma unroll
            for (int t = 0; t < 4; t++) {
                uint32_t ah[4], al[4];
                #pragma unroll
                for (int g = 0; g < 4; g++) {
                    const int fr = 2*t + (g >> 1);
                    const int b0 = (g & 1) * 2;
                    const float p0 = sf[fr][b0], p1 = sf[fr][b0+1];
                    const float h0 = __bfloat162float(__float2bfloat16(p0));
                    const float h1 = __bfloat162float(__float2bfloat16(p1));
                    ah[g] = pack_bf16x2(h0, h1);
                    al[g] = pack_bf16x2(p0 - h0, p1 - h1);
                }
                #pragma unroll
                for (int dg2 = 0; dg2 < 4; dg2++) {
                    uint32_t vh4[2][4], vl4[2][4];
                    #pragma unroll
                    for (int s = 0; s < 2; s++) {
                        const int dg = 2*dg2 + s;
                        const uint32_t vo = (uint32_t)((t*16 + vt_j + vt_r)*SSTR
                                                       + dg*16 + vt_d) * 2;
                        ldmatrix_x4_trans(vh4[s], cVh + vo);
                        ldmatrix_x4_trans(vl4[s], cVl + vo);
                    }
                    #pragma unroll
                    for (int s = 0; s < 2; s++) {
                        const int dg = 2*dg2 + s;
                        mma16816(of[2*dg],   ah, &vh4[s][0]);
                        mma16816(of[2*dg+1], ah, &vh4[s][2]);
                    }
                    #pragma unroll
                    for (int s = 0; s < 2; s++) {
                        const int dg = 2*dg2 + s;
                        mma16816(of[2*dg],   ah, &vl4[s][0]);
                        mma16816(of[2*dg+1], ah, &vl4[s][2]);
                    }
                    #pragma unroll
                    for (int s = 0; s < 2; s++) {
                        const int dg = 2*dg2 + s;
                        mma16816(of[2*dg],   al, &vh4[s][0]);
                        mma16816(of[2*dg+1], al, &vh4[s][2]);
                    }
                }
            }
        }
        __syncthreads();
    }

    // ---- write out: out[s'][b'][h*128+d] ----
    const float invlo = 1.f / l_lo;
    const float invhi = 1.f / l_hi;
    const int sqlo = s0 + qlo;
    const int sqhi = s0 + qhi;
    const size_t obase = (size_t)bp*1024 + h*128 + (lane & 3)*2;
    #pragma unroll
    for (int f = 0; f < 16; f++) {
        const int d = f*8;
        float2 o1; o1.x = of[f][0]*invlo; o1.y = of[f][1]*invlo;
        *(float2*)&out[(size_t)sqlo*2048 + obase + d] = o1;
        float2 o2; o2.x = of[f][2]*invhi; o2.y = of[f][3]*invhi;
        *(float2*)&out[(size_t)sqhi*2048 + obase + d] = o2;
    }
}

// ---------------------------------------------------------------------------
extern "C" void kernel_launch(void* const* d_in, const int* in_sizes, int n_in,
                              void* d_out, int out_size)
{
    (void)in_sizes; (void)n_in; (void)out_size;
    const float* val = (const float*)d_in[0];
    const float* Wq  = (const float*)d_in[1];
    const float* bq  = (const float*)d_in[2];
    const float* Wk  = (const float*)d_in[3];
    const float* bk  = (const float*)d_in[4];
    const float* Wv  = (const float*)d_in[5];
    const float* bv  = (const float*)d_in[6];
    float* out = (float*)d_out;

    cudaFuncSetAttribute(qkv_mma_kernel, cudaFuncAttributeMaxDynamicSharedMemorySize,
                         GEMM_SMEM);
    cudaFuncSetAttribute(attn_mma_kernel, cudaFuncAttributeMaxDynamicSharedMemorySize,
                         ATT_SMEM);

    convert_x_kernel<<<(8192*1024)/256, 256>>>(val);
    convert_w_kernel<<<(3*1024*1024)/256, 256>>>(Wq, Wk, Wv);
    {
        const int total = BATCH*HEADS * (2*WINW) * HD;
        zero_pads_kernel<<<(total + 255)/256, 256>>>();
    }
    {
        dim3 grid(1024/128, 8192/128, 3);
        qkv_mma_kernel<<<grid, 128, GEMM_SMEM>>>(bq, bk, bv);
    }
    {
        dim3 grid(S_LEN/128, HEADS, BATCH);
        attn_mma_kernel<<<grid, 256, ATT_SMEM>>>(out);
    }
}